// round 1
// baseline (speedup 1.0000x reference)
#include <cuda_runtime.h>
#include <cuda_bf16.h>
#include <cstddef>

// Problem constants
#define B_SZ   2
#define S_LEN  2048
#define DMODEL 1024
#define NHEAD  16
#define DK     64
#define NTOK   (B_SZ * S_LEN)          // 4096

// Scratch (allocation-free rule: __device__ globals)
__device__ float g_qp[NTOK * DMODEL];
__device__ float g_kp[NTOK * DMODEL];
__device__ float g_vp[NTOK * DMODEL];
__device__ float g_att[NTOK * DMODEL];

// ---------------------------------------------------------------------------
// SGEMM with bias: C[M,1024] = A[M,1024] @ W[1024,1024]^T + b
// 128x128 tile, BK=8, 256 threads, 8x8 per thread.
// ---------------------------------------------------------------------------
__global__ __launch_bounds__(256) void sgemm_bias(const float* __restrict__ A,
                                                  const float* __restrict__ W,
                                                  const float* __restrict__ bias,
                                                  float* __restrict__ C) {
    __shared__ float As[8][128];
    __shared__ float Bs[8][128];
    const int K = DMODEL;
    int tid = threadIdx.x;
    int m0 = blockIdx.y << 7;
    int n0 = blockIdx.x << 7;

    int lr = tid >> 1;            // 0..127 row within tile
    int lc = (tid & 1) << 2;      // 0 or 4 (float4 column group)
    const float* Ap = A + (size_t)(m0 + lr) * K + lc;
    const float* Wp = W + (size_t)(n0 + lr) * K + lc;

    int ty = tid >> 4, tx = tid & 15;
    float acc[8][8];
#pragma unroll
    for (int i = 0; i < 8; ++i)
#pragma unroll
        for (int j = 0; j < 8; ++j) acc[i][j] = 0.f;

    for (int k0 = 0; k0 < K; k0 += 8) {
        float4 av = *(const float4*)(Ap + k0);
        float4 wv = *(const float4*)(Wp + k0);
        As[lc + 0][lr] = av.x; As[lc + 1][lr] = av.y;
        As[lc + 2][lr] = av.z; As[lc + 3][lr] = av.w;
        Bs[lc + 0][lr] = wv.x; Bs[lc + 1][lr] = wv.y;
        Bs[lc + 2][lr] = wv.z; Bs[lc + 3][lr] = wv.w;
        __syncthreads();
#pragma unroll
        for (int kk = 0; kk < 8; ++kk) {
            float ar[8], br[8];
            *(float4*)&ar[0] = *(float4*)&As[kk][ty * 8];
            *(float4*)&ar[4] = *(float4*)&As[kk][ty * 8 + 4];
            *(float4*)&br[0] = *(float4*)&Bs[kk][tx * 8];
            *(float4*)&br[4] = *(float4*)&Bs[kk][tx * 8 + 4];
#pragma unroll
            for (int i = 0; i < 8; ++i)
#pragma unroll
                for (int j = 0; j < 8; ++j) acc[i][j] += ar[i] * br[j];
        }
        __syncthreads();
    }

#pragma unroll
    for (int i = 0; i < 8; ++i) {
        int m = m0 + ty * 8 + i;
#pragma unroll
        for (int j = 0; j < 8; j += 4) {
            int n = n0 + tx * 8 + j;
            float4 o;
            o.x = acc[i][j + 0] + bias[n + 0];
            o.y = acc[i][j + 1] + bias[n + 1];
            o.z = acc[i][j + 2] + bias[n + 2];
            o.w = acc[i][j + 3] + bias[n + 3];
            *(float4*)&C[(size_t)m * DMODEL + n] = o;
        }
    }
}

// ---------------------------------------------------------------------------
// Flash-attention style kernel. One block = (b, h, 64-row q tile).
// 256 threads, 16x16 grid, 4x4 microtile over (q rows, d cols) & (q, k).
// SMEM: QsT[d][q] pad68, KsT[d][k] pad68, Vs[k][d] pad64, Ss[q][k] pad65.
// ---------------------------------------------------------------------------
#define QP_PAD 68
#define SS_PAD 65
#define ATT_SMEM_FLOATS (64 * QP_PAD * 2 + 64 * 64 + 64 * SS_PAD + 3 * 64)
#define ATT_SMEM_BYTES (ATT_SMEM_FLOATS * 4)

__global__ __launch_bounds__(256) void attn_kernel(const float* __restrict__ QP,
                                                   const float* __restrict__ KP,
                                                   const float* __restrict__ VP,
                                                   float* __restrict__ OUT) {
    extern __shared__ float sm[];
    float* QsT   = sm;                      // 64*68
    float* KsT   = QsT + 64 * QP_PAD;       // 64*68
    float* Vs    = KsT + 64 * QP_PAD;       // 64*64
    float* Ss    = Vs + 64 * 64;            // 64*65
    float* row_m = Ss + 64 * SS_PAD;        // 64
    float* row_l = row_m + 64;              // 64
    float* row_c = row_l + 64;              // 64

    int tid = threadIdx.x;
    int qt = blockIdx.x, h = blockIdx.y, b = blockIdx.z;
    int s0 = qt * 64;
    size_t base = (size_t)b * S_LEN * DMODEL + (size_t)h * DK;

    // Load Q tile transposed, pre-scaled by 1/sqrt(DK) = 0.125
#pragma unroll
    for (int jj = 0; jj < 4; ++jj) {
        int slot = tid + 256 * jj;          // 0..1023
        int row = slot >> 4;
        int d4 = (slot & 15) << 2;
        float4 v = *(const float4*)&QP[base + (size_t)(s0 + row) * DMODEL + d4];
        QsT[(d4 + 0) * QP_PAD + row] = v.x * 0.125f;
        QsT[(d4 + 1) * QP_PAD + row] = v.y * 0.125f;
        QsT[(d4 + 2) * QP_PAD + row] = v.z * 0.125f;
        QsT[(d4 + 3) * QP_PAD + row] = v.w * 0.125f;
    }
    if (tid < 64) { row_m[tid] = -3e38f; row_l[tid] = 0.f; row_c[tid] = 1.f; }

    int tx = tid & 15, ty = tid >> 4;
    int q0 = ty * 4, d0 = tx * 4;           // d0 doubles as k-col base in QK step
    float acc[4][4];
#pragma unroll
    for (int i = 0; i < 4; ++i)
#pragma unroll
        for (int j = 0; j < 4; ++j) acc[i][j] = 0.f;

    int w = tid >> 5, lane = tid & 31;

    for (int kt = 0; kt < S_LEN / 64; ++kt) {
        int ks = kt * 64;
        // load K (transposed) and V (natural) tiles
#pragma unroll
        for (int jj = 0; jj < 4; ++jj) {
            int slot = tid + 256 * jj;
            int row = slot >> 4;
            int d4 = (slot & 15) << 2;
            float4 kv = *(const float4*)&KP[base + (size_t)(ks + row) * DMODEL + d4];
            KsT[(d4 + 0) * QP_PAD + row] = kv.x;
            KsT[(d4 + 1) * QP_PAD + row] = kv.y;
            KsT[(d4 + 2) * QP_PAD + row] = kv.z;
            KsT[(d4 + 3) * QP_PAD + row] = kv.w;
            float4 vv = *(const float4*)&VP[base + (size_t)(ks + row) * DMODEL + d4];
            *(float4*)&Vs[row * 64 + d4] = vv;
        }
        __syncthreads();

        // S = Q @ K^T (already scaled)
        float sacc[4][4];
#pragma unroll
        for (int i = 0; i < 4; ++i)
#pragma unroll
            for (int j = 0; j < 4; ++j) sacc[i][j] = 0.f;
#pragma unroll 8
        for (int d = 0; d < DK; ++d) {
            float4 qa = *(float4*)&QsT[d * QP_PAD + q0];
            float4 kb = *(float4*)&KsT[d * QP_PAD + d0];
            float ar[4] = {qa.x, qa.y, qa.z, qa.w};
            float br[4] = {kb.x, kb.y, kb.z, kb.w};
#pragma unroll
            for (int i = 0; i < 4; ++i)
#pragma unroll
                for (int j = 0; j < 4; ++j) sacc[i][j] += ar[i] * br[j];
        }
#pragma unroll
        for (int i = 0; i < 4; ++i)
#pragma unroll
            for (int j = 0; j < 4; ++j) Ss[(q0 + i) * SS_PAD + d0 + j] = sacc[i][j];
        __syncthreads();

        // Online softmax: warp w owns rows w*8 .. w*8+7
#pragma unroll
        for (int rr = 0; rr < 8; ++rr) {
            int r = w * 8 + rr;
            float v0 = Ss[r * SS_PAD + lane];
            float v1 = Ss[r * SS_PAD + 32 + lane];
            float mx = fmaxf(v0, v1);
#pragma unroll
            for (int off = 16; off > 0; off >>= 1)
                mx = fmaxf(mx, __shfl_xor_sync(0xffffffffu, mx, off));
            float mold = row_m[r];
            float mnew = fmaxf(mold, mx);
            float p0 = __expf(v0 - mnew);
            float p1 = __expf(v1 - mnew);
            Ss[r * SS_PAD + lane] = p0;
            Ss[r * SS_PAD + 32 + lane] = p1;
            float s = p0 + p1;
#pragma unroll
            for (int off = 16; off > 0; off >>= 1)
                s += __shfl_xor_sync(0xffffffffu, s, off);
            if (lane == 0) {
                float corr = __expf(mold - mnew);
                row_c[r] = corr;
                row_l[r] = row_l[r] * corr + s;
                row_m[r] = mnew;
            }
        }
        __syncthreads();

        // Rescale accumulator and add P @ V
#pragma unroll
        for (int i = 0; i < 4; ++i) {
            float cf = row_c[q0 + i];
#pragma unroll
            for (int j = 0; j < 4; ++j) acc[i][j] *= cf;
        }
#pragma unroll 8
        for (int kk = 0; kk < 64; ++kk) {
            float4 vv = *(float4*)&Vs[kk * 64 + d0];
            float vr[4] = {vv.x, vv.y, vv.z, vv.w};
            float pr[4];
#pragma unroll
            for (int i = 0; i < 4; ++i) pr[i] = Ss[(q0 + i) * SS_PAD + kk];
#pragma unroll
            for (int i = 0; i < 4; ++i)
#pragma unroll
                for (int j = 0; j < 4; ++j) acc[i][j] += pr[i] * vr[j];
        }
        __syncthreads();    // protect Ks/Vs/Ss before next tile overwrite
    }

    // Epilogue: divide by l, write out
#pragma unroll
    for (int i = 0; i < 4; ++i) {
        float inv = 1.0f / row_l[q0 + i];
        float4 o;
        o.x = acc[i][0] * inv; o.y = acc[i][1] * inv;
        o.z = acc[i][2] * inv; o.w = acc[i][3] * inv;
        *(float4*)&OUT[base + (size_t)(s0 + q0 + i) * DMODEL + d0] = o;
    }
}

// ---------------------------------------------------------------------------
extern "C" void kernel_launch(void* const* d_in, const int* in_sizes, int n_in,
                              void* d_out, int out_size) {
    const float* v  = (const float*)d_in[0];
    const float* k  = (const float*)d_in[1];
    const float* q  = (const float*)d_in[2];
    const float* Wv = (const float*)d_in[3];
    const float* bv = (const float*)d_in[4];
    const float* Wk = (const float*)d_in[5];
    const float* bk = (const float*)d_in[6];
    const float* Wq = (const float*)d_in[7];
    const float* bq = (const float*)d_in[8];
    const float* Wo = (const float*)d_in[9];
    const float* bo = (const float*)d_in[10];

    float *qp, *kp, *vp, *att;
    cudaGetSymbolAddress((void**)&qp, g_qp);
    cudaGetSymbolAddress((void**)&kp, g_kp);
    cudaGetSymbolAddress((void**)&vp, g_vp);
    cudaGetSymbolAddress((void**)&att, g_att);

    dim3 gg(DMODEL / 128, NTOK / 128);   // (8, 32)
    dim3 bb(256);
    sgemm_bias<<<gg, bb>>>(q, Wq, bq, qp);
    sgemm_bias<<<gg, bb>>>(k, Wk, bk, kp);
    sgemm_bias<<<gg, bb>>>(v, Wv, bv, vp);

    cudaFuncSetAttribute(attn_kernel, cudaFuncAttributeMaxDynamicSharedMemorySize,
                         ATT_SMEM_BYTES);
    attn_kernel<<<dim3(S_LEN / 64, NHEAD, B_SZ), 256, ATT_SMEM_BYTES>>>(qp, kp, vp, att);

    sgemm_bias<<<gg, bb>>>(att, Wo, bo, (float*)d_out);
}

// round 3
// speedup vs baseline: 2.1098x; 2.1098x over previous
#include <cuda_runtime.h>
#include <cuda_bf16.h>
#include <cstdint>
#include <cstddef>

#define S_LEN  2048
#define DMODEL 1024
#define NHEAD  16
#define DK     64
#define NTOK   4096

// ===================== low-level helpers (base sm_103 target safe) =====================
__device__ __forceinline__ uint32_t smem_u32(const void* p) {
    uint32_t a;
    asm("{ .reg .u64 t; cvta.to.shared.u64 t, %1; cvt.u32.u64 %0, t; }" : "=r"(a) : "l"(p));
    return a;
}
#define CP16(dst, src) \
    asm volatile("cp.async.cg.shared.global [%0], [%1], 16;" :: "r"(dst), "l"(src))
#define CP_COMMIT() asm volatile("cp.async.commit_group;" ::: "memory")
#define CP_WAIT(n)  asm volatile("cp.async.wait_group %0;" :: "n"(n) : "memory")
#define LDSM4(d, addr) \
    asm volatile("ldmatrix.sync.aligned.m8n8.x4.shared.b16 {%0,%1,%2,%3}, [%4];" \
        : "=r"((d)[0]), "=r"((d)[1]), "=r"((d)[2]), "=r"((d)[3]) : "r"(addr))
#define MMA_BF16(c, a, b) \
    asm volatile("mma.sync.aligned.m16n8k16.row.col.f32.bf16.bf16.f32 " \
        "{%0,%1,%2,%3}, {%4,%5,%6,%7}, {%8,%9}, {%0,%1,%2,%3};" \
        : "+f"((c)[0]), "+f"((c)[1]), "+f"((c)[2]), "+f"((c)[3]) \
        : "r"((a)[0]), "r"((a)[1]), "r"((a)[2]), "r"((a)[3]), "r"((b)[0]), "r"((b)[1]))

__device__ __forceinline__ void split2(float v, __nv_bfloat16& h, __nv_bfloat16& l) {
    h = __float2bfloat16(v);
    l = __float2bfloat16(v - __bfloat162float(h));
}

// ===================== scratch =====================
__device__ __nv_bfloat16 g_qh[NTOK*DMODEL], g_ql[NTOK*DMODEL];
__device__ __nv_bfloat16 g_kh[NTOK*DMODEL], g_kl[NTOK*DMODEL];
__device__ __nv_bfloat16 g_vh[NTOK*DMODEL], g_vl[NTOK*DMODEL];
__device__ __nv_bfloat16 g_Wqh[DMODEL*DMODEL], g_Wql[DMODEL*DMODEL];
__device__ __nv_bfloat16 g_Wkh[DMODEL*DMODEL], g_Wkl[DMODEL*DMODEL];
__device__ __nv_bfloat16 g_Wvh[DMODEL*DMODEL], g_Wvl[DMODEL*DMODEL];
__device__ __nv_bfloat16 g_Woh[DMODEL*DMODEL], g_Wol[DMODEL*DMODEL];
__device__ __nv_bfloat16 g_qph[NTOK*DMODEL], g_qpl[NTOK*DMODEL];
__device__ __nv_bfloat16 g_kph[NTOK*DMODEL], g_kpl[NTOK*DMODEL];
__device__ __nv_bfloat16 g_vTh[2*NHEAD*DK*S_LEN], g_vTl[2*NHEAD*DK*S_LEN];
__device__ __nv_bfloat16 g_ath[NTOK*DMODEL], g_atl[NTOK*DMODEL];
__device__ float g_scores[(size_t)2*NHEAD*S_LEN*S_LEN];   // 512MB; becomes P hi/lo in place

// ===================== fp32 -> (bf16 hi, bf16 lo) =====================
__global__ __launch_bounds__(256) void cvt_split(const float* __restrict__ src,
                                                 __nv_bfloat16* __restrict__ hi,
                                                 __nv_bfloat16* __restrict__ lo, int n) {
    int i = (blockIdx.x * blockDim.x + threadIdx.x) * 4;
    if (i < n) {
        float4 v = *(const float4*)(src + i);
        __nv_bfloat16 h0, h1, h2, h3, l0, l1, l2, l3;
        split2(v.x, h0, l0); split2(v.y, h1, l1);
        split2(v.z, h2, l2); split2(v.w, h3, l3);
        *(__nv_bfloat162*)(hi + i)     = __nv_bfloat162(h0, h1);
        *(__nv_bfloat162*)(hi + i + 2) = __nv_bfloat162(h2, h3);
        *(__nv_bfloat162*)(lo + i)     = __nv_bfloat162(l0, l1);
        *(__nv_bfloat162*)(lo + i + 2) = __nv_bfloat162(l2, l3);
    }
}

// ===================== generic HMMA bf16x3 GEMM =====================
// C[m,n] = sum_k A[m,k]*B[n,k] with A,B split hi/lo (3 accumulated products).
// CTA tile BM x BN, BK=32, 256 threads = 8 warps, warp tile 64x32.
// EP: 0 fp32+bias | 1 bf16 hi/lo (+bias)*scale | 2 fp32 raw | 3 bf16 hi/lo V-transposed
template <int BM, int BN, int EP>
__global__ __launch_bounds__(256, 1) void gemm_hmma(
    const __nv_bfloat16* __restrict__ Ahi, const __nv_bfloat16* __restrict__ Alo,
    const __nv_bfloat16* __restrict__ Bhi, const __nv_bfloat16* __restrict__ Blo,
    int K, int ldA, int ldB,
    long long aOffB, long long aOffH, long long bOffB, long long bOffH,
    float* __restrict__ C32, __nv_bfloat16* __restrict__ Chi, __nv_bfloat16* __restrict__ Clo,
    const float* __restrict__ bias, float scale,
    long long cOffB, long long cOffH, int ldC)
{
    constexpr int WARPS_N = BN / 32;
    constexpr int SA = BM * 80;           // padded row: 32 bf16 -> 40 slots -> 80B
    constexpr int SB = BN * 80;
    constexpr int STAGE = 2 * SA + 2 * SB;
    extern __shared__ char smem[];
    const uint32_t sbase = smem_u32(smem);

    const int tid = threadIdx.x;
    const int warp = tid >> 5, lane = tid & 31;
    const int warpM = warp / WARPS_N, warpN = warp % WARPS_N;
    const int wm0 = warpM * 64, wn0 = warpN * 32;
    const int m0 = blockIdx.y * BM;
    const int n0 = blockIdx.x * BN;
    const int zb = blockIdx.z >> 4, zh = blockIdx.z & 15;

    const char* Ah = (const char*)(Ahi + aOffB * zb + aOffH * zh);
    const char* Al = (const char*)(Alo + aOffB * zb + aOffH * zh);
    const char* Bh = (const char*)(Bhi + bOffB * zb + bOffH * zh);
    const char* Bl = (const char*)(Blo + bOffB * zb + bOffH * zh);

    float acc[4][4][4];
#pragma unroll
    for (int i = 0; i < 4; ++i)
#pragma unroll
        for (int j = 0; j < 4; ++j)
#pragma unroll
            for (int e = 0; e < 4; ++e) acc[i][j][e] = 0.f;

    const int chunks = K >> 5;   // BK = 32

    auto load_chunk = [&](int c, int buf) {
        const uint32_t s = sbase + buf * STAGE;
        const long long kB = (long long)c * 64;   // 32 elems * 2B
#pragma unroll 2
        for (int u = tid; u < BM * 4; u += 256) {
            int r = u >> 2, cc = u & 3;
            long long go = ((long long)(m0 + r) * ldA) * 2 + kB + cc * 16;
            uint32_t so = r * 80 + cc * 16;
            CP16(s + so, Ah + go);
            CP16(s + SA + so, Al + go);
        }
#pragma unroll 2
        for (int u = tid; u < BN * 4; u += 256) {
            int r = u >> 2, cc = u & 3;
            long long go = ((long long)(n0 + r) * ldB) * 2 + kB + cc * 16;
            uint32_t so = r * 80 + cc * 16;
            CP16(s + 2 * SA + so, Bh + go);
            CP16(s + 2 * SA + SB + so, Bl + go);
        }
        CP_COMMIT();
    };

    // per-lane ldmatrix base addresses (offsets within a stage)
    const uint32_t aAddr = (wm0 + (lane & 15)) * 80 + (lane >> 4) * 16;
    const int g = lane >> 3;
    const uint32_t bAddr = 2 * SA + (wn0 + (g >> 1) * 8 + (lane & 7)) * 80 + (g & 1) * 16;

    load_chunk(0, 0);

    for (int c = 0; c < chunks; ++c) {
        const int buf = c & 1;
        if (c + 1 < chunks) {
            load_chunk(c + 1, buf ^ 1);
            CP_WAIT(1);
        } else {
            CP_WAIT(0);
        }
        __syncthreads();

        const uint32_t s = sbase + buf * STAGE;
#pragma unroll
        for (int ks = 0; ks < 2; ++ks) {
            const uint32_t kb = ks * 32;    // 16 elems * 2B
            uint32_t ah[4][4], al[4][4];
#pragma unroll
            for (int mt = 0; mt < 4; ++mt) {
                LDSM4(ah[mt], s + aAddr + mt * 16 * 80 + kb);
                LDSM4(al[mt], s + SA + aAddr + mt * 16 * 80 + kb);
            }
            uint32_t bh[4][2], bl[4][2];
#pragma unroll
            for (int ntp = 0; ntp < 2; ++ntp) {
                uint32_t t[4];
                LDSM4(t, s + bAddr + ntp * 16 * 80 + kb);
                bh[ntp*2][0] = t[0]; bh[ntp*2][1] = t[1];
                bh[ntp*2+1][0] = t[2]; bh[ntp*2+1][1] = t[3];
                LDSM4(t, s + SB + bAddr + ntp * 16 * 80 + kb);
                bl[ntp*2][0] = t[0]; bl[ntp*2][1] = t[1];
                bl[ntp*2+1][0] = t[2]; bl[ntp*2+1][1] = t[3];
            }
#pragma unroll
            for (int mt = 0; mt < 4; ++mt)
#pragma unroll
                for (int nt = 0; nt < 4; ++nt) {
                    MMA_BF16(acc[mt][nt], ah[mt], bh[nt]);
                    MMA_BF16(acc[mt][nt], ah[mt], bl[nt]);
                    MMA_BF16(acc[mt][nt], al[mt], bh[nt]);
                }
        }
        __syncthreads();
    }

    // ---------------- epilogue (direct gmem, no smem reuse) ----------------
    const long long cbase = cOffB * zb + cOffH * zh;
#pragma unroll
    for (int mt = 0; mt < 4; ++mt) {
#pragma unroll
        for (int nt = 0; nt < 4; ++nt) {
            int row0 = m0 + wm0 + mt * 16 + (lane >> 2);
            int row1 = row0 + 8;
            int col = n0 + wn0 + nt * 8 + (lane & 3) * 2;
            float p0 = acc[mt][nt][0], p1 = acc[mt][nt][1];
            float p2 = acc[mt][nt][2], p3 = acc[mt][nt][3];
            if (EP == 0) {
                float b0 = bias[col], b1 = bias[col + 1];
                float2 o0 = make_float2(p0 + b0, p1 + b1);
                float2 o1 = make_float2(p2 + b0, p3 + b1);
                *(float2*)&C32[cbase + (long long)row0 * ldC + col] = o0;
                *(float2*)&C32[cbase + (long long)row1 * ldC + col] = o1;
            } else if (EP == 2) {
                *(float2*)&C32[cbase + (long long)row0 * ldC + col] = make_float2(p0, p1);
                *(float2*)&C32[cbase + (long long)row1 * ldC + col] = make_float2(p2, p3);
            } else if (EP == 1) {
                float b0 = bias ? bias[col] : 0.f, b1 = bias ? bias[col + 1] : 0.f;
                float v0 = (p0 + b0) * scale, v1 = (p1 + b1) * scale;
                float v2 = (p2 + b0) * scale, v3 = (p3 + b1) * scale;
                __nv_bfloat16 h0, h1, h2, h3, l0, l1, l2, l3;
                split2(v0, h0, l0); split2(v1, h1, l1);
                split2(v2, h2, l2); split2(v3, h3, l3);
                *(__nv_bfloat162*)&Chi[cbase + (long long)row0 * ldC + col] = __nv_bfloat162(h0, h1);
                *(__nv_bfloat162*)&Chi[cbase + (long long)row1 * ldC + col] = __nv_bfloat162(h2, h3);
                *(__nv_bfloat162*)&Clo[cbase + (long long)row0 * ldC + col] = __nv_bfloat162(l0, l1);
                *(__nv_bfloat162*)&Clo[cbase + (long long)row1 * ldC + col] = __nv_bfloat162(l2, l3);
            } else {  // EP == 3 : V projection, per-head transposed [b][h][d][s]
                float vals[4] = { p0, p1, p2, p3 };
                int rows[4] = { row0, row0, row1, row1 };
                int cols[4] = { col, col + 1, col, col + 1 };
#pragma unroll
                for (int e = 0; e < 4; ++e) {
                    float v = vals[e] + bias[cols[e]];
                    __nv_bfloat16 h, l; split2(v, h, l);
                    int bidx = rows[e] >> 11, sidx = rows[e] & 2047;
                    int hd = cols[e] >> 6, d = cols[e] & 63;
                    long long dst = ((long long)bidx * NHEAD + hd) * (DK * S_LEN)
                                  + (long long)d * S_LEN + sidx;
                    Chi[dst] = h; Clo[dst] = l;
                }
            }
        }
    }
}

// ===================== softmax: fp32 row -> P hi/lo bf16 in place =====================
__global__ __launch_bounds__(256) void softmax_rows(float* __restrict__ scores) {
    const int w = threadIdx.x >> 5, lane = threadIdx.x & 31;
    const long long rowid = (long long)blockIdx.x * 8 + w;
    float* rowp = scores + rowid * S_LEN;
    float4 v[16];
    float mx = -3e38f;
#pragma unroll
    for (int i = 0; i < 16; ++i) {
        v[i] = *(const float4*)(rowp + i * 128 + lane * 4);
        mx = fmaxf(mx, fmaxf(fmaxf(v[i].x, v[i].y), fmaxf(v[i].z, v[i].w)));
    }
#pragma unroll
    for (int o = 16; o; o >>= 1) mx = fmaxf(mx, __shfl_xor_sync(0xffffffffu, mx, o));
    float s = 0.f;
#pragma unroll
    for (int i = 0; i < 16; ++i) {
        v[i].x = __expf(v[i].x - mx); v[i].y = __expf(v[i].y - mx);
        v[i].z = __expf(v[i].z - mx); v[i].w = __expf(v[i].w - mx);
        s += (v[i].x + v[i].y) + (v[i].z + v[i].w);
    }
#pragma unroll
    for (int o = 16; o; o >>= 1) s += __shfl_xor_sync(0xffffffffu, s, o);
    const float inv = 1.0f / s;
    __syncwarp();
    __nv_bfloat16* hip = (__nv_bfloat16*)rowp;   // first half of the 8KB row
    __nv_bfloat16* lop = hip + S_LEN;            // second half
#pragma unroll
    for (int i = 0; i < 16; ++i) {
        int j = i * 128 + lane * 4;
        float p0 = v[i].x * inv, p1 = v[i].y * inv, p2 = v[i].z * inv, p3 = v[i].w * inv;
        __nv_bfloat16 h0, h1, h2, h3, l0, l1, l2, l3;
        split2(p0, h0, l0); split2(p1, h1, l1); split2(p2, h2, l2); split2(p3, h3, l3);
        *(__nv_bfloat162*)(hip + j)     = __nv_bfloat162(h0, h1);
        *(__nv_bfloat162*)(hip + j + 2) = __nv_bfloat162(h2, h3);
        *(__nv_bfloat162*)(lop + j)     = __nv_bfloat162(l0, l1);
        *(__nv_bfloat162*)(lop + j + 2) = __nv_bfloat162(l2, l3);
    }
}

// ===================== host =====================
static inline void* sym(const void* s) { void* p; cudaGetSymbolAddress(&p, s); return p; }

extern "C" void kernel_launch(void* const* d_in, const int* in_sizes, int n_in,
                              void* d_out, int out_size) {
    const float* v  = (const float*)d_in[0];
    const float* k  = (const float*)d_in[1];
    const float* q  = (const float*)d_in[2];
    const float* Wv = (const float*)d_in[3];
    const float* bv = (const float*)d_in[4];
    const float* Wk = (const float*)d_in[5];
    const float* bk = (const float*)d_in[6];
    const float* Wq = (const float*)d_in[7];
    const float* bq = (const float*)d_in[8];
    const float* Wo = (const float*)d_in[9];
    const float* bo = (const float*)d_in[10];

    __nv_bfloat16 *qh=(__nv_bfloat16*)sym(g_qh), *ql=(__nv_bfloat16*)sym(g_ql);
    __nv_bfloat16 *kh=(__nv_bfloat16*)sym(g_kh), *kl=(__nv_bfloat16*)sym(g_kl);
    __nv_bfloat16 *vh=(__nv_bfloat16*)sym(g_vh), *vl=(__nv_bfloat16*)sym(g_vl);
    __nv_bfloat16 *Wqh=(__nv_bfloat16*)sym(g_Wqh), *Wql=(__nv_bfloat16*)sym(g_Wql);
    __nv_bfloat16 *Wkh=(__nv_bfloat16*)sym(g_Wkh), *Wkl=(__nv_bfloat16*)sym(g_Wkl);
    __nv_bfloat16 *Wvh=(__nv_bfloat16*)sym(g_Wvh), *Wvl=(__nv_bfloat16*)sym(g_Wvl);
    __nv_bfloat16 *Woh=(__nv_bfloat16*)sym(g_Woh), *Wol=(__nv_bfloat16*)sym(g_Wol);
    __nv_bfloat16 *qph=(__nv_bfloat16*)sym(g_qph), *qpl=(__nv_bfloat16*)sym(g_qpl);
    __nv_bfloat16 *kph=(__nv_bfloat16*)sym(g_kph), *kpl=(__nv_bfloat16*)sym(g_kpl);
    __nv_bfloat16 *vTh=(__nv_bfloat16*)sym(g_vTh), *vTl=(__nv_bfloat16*)sym(g_vTl);
    __nv_bfloat16 *ath=(__nv_bfloat16*)sym(g_ath), *atl=(__nv_bfloat16*)sym(g_atl);
    float* scores = (float*)sym(g_scores);

    // dynamic smem: (BM+BN)*160 bytes per stage, 2 stages
    const int SM_128 = 2 * (128 + 128) * 160;   // 81920
    const int SM_256 = 2 * (256 + 64) * 160;    // 102400
    cudaFuncSetAttribute(gemm_hmma<128,128,0>, cudaFuncAttributeMaxDynamicSharedMemorySize, SM_128);
    cudaFuncSetAttribute(gemm_hmma<128,128,1>, cudaFuncAttributeMaxDynamicSharedMemorySize, SM_128);
    cudaFuncSetAttribute(gemm_hmma<128,128,2>, cudaFuncAttributeMaxDynamicSharedMemorySize, SM_128);
    cudaFuncSetAttribute(gemm_hmma<128,128,3>, cudaFuncAttributeMaxDynamicSharedMemorySize, SM_128);
    cudaFuncSetAttribute(gemm_hmma<256,64,1>,  cudaFuncAttributeMaxDynamicSharedMemorySize, SM_256);

    // --- split conversions ---
    cvt_split<<<4096, 256>>>(q, qh, ql, NTOK * DMODEL);
    cvt_split<<<4096, 256>>>(k, kh, kl, NTOK * DMODEL);
    cvt_split<<<4096, 256>>>(v, vh, vl, NTOK * DMODEL);
    cvt_split<<<1024, 256>>>(Wq, Wqh, Wql, DMODEL * DMODEL);
    cvt_split<<<1024, 256>>>(Wk, Wkh, Wkl, DMODEL * DMODEL);
    cvt_split<<<1024, 256>>>(Wv, Wvh, Wvl, DMODEL * DMODEL);
    cvt_split<<<1024, 256>>>(Wo, Woh, Wol, DMODEL * DMODEL);

    // --- projections (fold 1/sqrt(DK)=0.125 into Q) ---
    dim3 gp(8, 32, 1);
    gemm_hmma<128,128,1><<<gp, 256, SM_128>>>(qh, ql, Wqh, Wql, 1024, 1024, 1024,
        0, 0, 0, 0, nullptr, qph, qpl, bq, 0.125f, 0, 0, 1024);
    gemm_hmma<128,128,1><<<gp, 256, SM_128>>>(kh, kl, Wkh, Wkl, 1024, 1024, 1024,
        0, 0, 0, 0, nullptr, kph, kpl, bk, 1.0f, 0, 0, 1024);
    gemm_hmma<128,128,3><<<gp, 256, SM_128>>>(vh, vl, Wvh, Wvl, 1024, 1024, 1024,
        0, 0, 0, 0, nullptr, vTh, vTl, bv, 1.0f, 0, 0, 1024);

    // --- scores = (Q/8) @ K^T per (b,h) ---
    gemm_hmma<128,128,2><<<dim3(16, 16, 32), 256, SM_128>>>(qph, qpl, kph, kpl, 64, 1024, 1024,
        (long long)2048 * 1024, 64, (long long)2048 * 1024, 64,
        scores, nullptr, nullptr, nullptr, 1.0f,
        (long long)16 * 2048 * 2048, (long long)2048 * 2048, 2048);

    // --- softmax + in-place bf16 hi/lo split ---
    softmax_rows<<<(2 * NHEAD * S_LEN) / 8, 256>>>(scores);

    // --- O = P @ V per (b,h) ---
    const __nv_bfloat16* Ph = (const __nv_bfloat16*)scores;
    gemm_hmma<256,64,1><<<dim3(1, 8, 32), 256, SM_256>>>(Ph, Ph + 2048, vTh, vTl, 2048, 4096, 2048,
        (long long)16 * 2048 * 4096, (long long)2048 * 4096,
        (long long)16 * 64 * 2048, (long long)64 * 2048,
        nullptr, ath, atl, nullptr, 1.0f,
        (long long)2048 * 1024, 64, 1024);

    // --- final projection ---
    gemm_hmma<128,128,0><<<gp, 256, SM_128>>>(ath, atl, Woh, Wol, 1024, 1024, 1024,
        0, 0, 0, 0, (float*)d_out, nullptr, nullptr, bo, 1.0f, 0, 0, 1024);
}

// round 4
// speedup vs baseline: 2.9606x; 1.4033x over previous
#include <cuda_runtime.h>
#include <cuda_bf16.h>
#include <cstdint>
#include <cstddef>

#define S_LEN  2048
#define DMODEL 1024
#define NHEAD  16
#define DK     64
#define NTOK   4096

// ===================== low-level helpers (base sm_103 target safe) =====================
__device__ __forceinline__ uint32_t smem_u32(const void* p) {
    uint32_t a;
    asm("{ .reg .u64 t; cvta.to.shared.u64 t, %1; cvt.u32.u64 %0, t; }" : "=r"(a) : "l"(p));
    return a;
}
#define CP16(dst, src) \
    asm volatile("cp.async.cg.shared.global [%0], [%1], 16;" :: "r"(dst), "l"(src))
#define CP_COMMIT() asm volatile("cp.async.commit_group;" ::: "memory")
#define CP_WAIT(n)  asm volatile("cp.async.wait_group %0;" :: "n"(n) : "memory")
#define LDSM4(d, addr) \
    asm volatile("ldmatrix.sync.aligned.m8n8.x4.shared.b16 {%0,%1,%2,%3}, [%4];" \
        : "=r"((d)[0]), "=r"((d)[1]), "=r"((d)[2]), "=r"((d)[3]) : "r"(addr))
#define MMA_BF16(c, a, b) \
    asm volatile("mma.sync.aligned.m16n8k16.row.col.f32.bf16.bf16.f32 " \
        "{%0,%1,%2,%3}, {%4,%5,%6,%7}, {%8,%9}, {%0,%1,%2,%3};" \
        : "+f"((c)[0]), "+f"((c)[1]), "+f"((c)[2]), "+f"((c)[3]) \
        : "r"((a)[0]), "r"((a)[1]), "r"((a)[2]), "r"((a)[3]), "r"((b)[0]), "r"((b)[1]))

__device__ __forceinline__ void split2(float v, __nv_bfloat16& h, __nv_bfloat16& l) {
    h = __float2bfloat16(v);
    l = __float2bfloat16(v - __bfloat162float(h));
}
// split two floats -> packed bf16x2 hi and lo words
__device__ __forceinline__ void split_pack(float x, float y, uint32_t& hp, uint32_t& lp) {
    __nv_bfloat16 hx, lx, hy, ly;
    split2(x, hx, lx); split2(y, hy, ly);
    __nv_bfloat162 h2(hx, hy), l2(lx, ly);
    hp = *reinterpret_cast<uint32_t*>(&h2);
    lp = *reinterpret_cast<uint32_t*>(&l2);
}

// ===================== scratch =====================
__device__ __nv_bfloat16 g_qh[NTOK*DMODEL], g_ql[NTOK*DMODEL];
__device__ __nv_bfloat16 g_kh[NTOK*DMODEL], g_kl[NTOK*DMODEL];
__device__ __nv_bfloat16 g_vh[NTOK*DMODEL], g_vl[NTOK*DMODEL];
__device__ __nv_bfloat16 g_Wqh[DMODEL*DMODEL], g_Wql[DMODEL*DMODEL];
__device__ __nv_bfloat16 g_Wkh[DMODEL*DMODEL], g_Wkl[DMODEL*DMODEL];
__device__ __nv_bfloat16 g_Wvh[DMODEL*DMODEL], g_Wvl[DMODEL*DMODEL];
__device__ __nv_bfloat16 g_Woh[DMODEL*DMODEL], g_Wol[DMODEL*DMODEL];
__device__ __nv_bfloat16 g_qph[NTOK*DMODEL], g_qpl[NTOK*DMODEL];
__device__ __nv_bfloat16 g_kph[NTOK*DMODEL], g_kpl[NTOK*DMODEL];
__device__ __nv_bfloat16 g_vTh[2*NHEAD*DK*S_LEN], g_vTl[2*NHEAD*DK*S_LEN];
__device__ __nv_bfloat16 g_ath[NTOK*DMODEL], g_atl[NTOK*DMODEL];

// ===================== fp32 -> (bf16 hi, bf16 lo) =====================
__global__ __launch_bounds__(256) void cvt_split(const float* __restrict__ src,
                                                 __nv_bfloat16* __restrict__ hi,
                                                 __nv_bfloat16* __restrict__ lo, int n) {
    int i = (blockIdx.x * blockDim.x + threadIdx.x) * 4;
    if (i < n) {
        float4 v = *(const float4*)(src + i);
        __nv_bfloat16 h0, h1, h2, h3, l0, l1, l2, l3;
        split2(v.x, h0, l0); split2(v.y, h1, l1);
        split2(v.z, h2, l2); split2(v.w, h3, l3);
        *(__nv_bfloat162*)(hi + i)     = __nv_bfloat162(h0, h1);
        *(__nv_bfloat162*)(hi + i + 2) = __nv_bfloat162(h2, h3);
        *(__nv_bfloat162*)(lo + i)     = __nv_bfloat162(l0, l1);
        *(__nv_bfloat162*)(lo + i + 2) = __nv_bfloat162(l2, l3);
    }
}

// ===================== generic HMMA bf16x3 GEMM (projections / final) =====================
// EP: 0 fp32+bias | 1 bf16 hi/lo (+bias)*scale | 3 bf16 hi/lo V-transposed
template <int BM, int BN, int EP>
__global__ __launch_bounds__(256, 1) void gemm_hmma(
    const __nv_bfloat16* __restrict__ Ahi, const __nv_bfloat16* __restrict__ Alo,
    const __nv_bfloat16* __restrict__ Bhi, const __nv_bfloat16* __restrict__ Blo,
    int K, int ldA, int ldB,
    float* __restrict__ C32, __nv_bfloat16* __restrict__ Chi, __nv_bfloat16* __restrict__ Clo,
    const float* __restrict__ bias, float scale, int ldC)
{
    constexpr int WARPS_N = BN / 32;
    constexpr int SA = BM * 80;
    constexpr int SB = BN * 80;
    constexpr int STAGE = 2 * SA + 2 * SB;
    extern __shared__ char smem[];
    const uint32_t sbase = smem_u32(smem);

    const int tid = threadIdx.x;
    const int warp = tid >> 5, lane = tid & 31;
    const int warpM = warp / WARPS_N, warpN = warp % WARPS_N;
    const int wm0 = warpM * 64, wn0 = warpN * 32;
    const int m0 = blockIdx.y * BM;
    const int n0 = blockIdx.x * BN;

    const char* Ah = (const char*)Ahi;
    const char* Al = (const char*)Alo;
    const char* Bh = (const char*)Bhi;
    const char* Bl = (const char*)Blo;

    float acc[4][4][4];
#pragma unroll
    for (int i = 0; i < 4; ++i)
#pragma unroll
        for (int j = 0; j < 4; ++j)
#pragma unroll
            for (int e = 0; e < 4; ++e) acc[i][j][e] = 0.f;

    const int chunks = K >> 5;

    auto load_chunk = [&](int c, int buf) {
        const uint32_t s = sbase + buf * STAGE;
        const long long kB = (long long)c * 64;
#pragma unroll 2
        for (int u = tid; u < BM * 4; u += 256) {
            int r = u >> 2, cc = u & 3;
            long long go = ((long long)(m0 + r) * ldA) * 2 + kB + cc * 16;
            uint32_t so = r * 80 + cc * 16;
            CP16(s + so, Ah + go);
            CP16(s + SA + so, Al + go);
        }
#pragma unroll 2
        for (int u = tid; u < BN * 4; u += 256) {
            int r = u >> 2, cc = u & 3;
            long long go = ((long long)(n0 + r) * ldB) * 2 + kB + cc * 16;
            uint32_t so = r * 80 + cc * 16;
            CP16(s + 2 * SA + so, Bh + go);
            CP16(s + 2 * SA + SB + so, Bl + go);
        }
        CP_COMMIT();
    };

    const uint32_t aAddr = (wm0 + (lane & 15)) * 80 + (lane >> 4) * 16;
    const int g = lane >> 3;
    const uint32_t bAddr = 2 * SA + (wn0 + (g >> 1) * 8 + (lane & 7)) * 80 + (g & 1) * 16;

    load_chunk(0, 0);

    for (int c = 0; c < chunks; ++c) {
        const int buf = c & 1;
        if (c + 1 < chunks) {
            load_chunk(c + 1, buf ^ 1);
            CP_WAIT(1);
        } else {
            CP_WAIT(0);
        }
        __syncthreads();

        const uint32_t s = sbase + buf * STAGE;
#pragma unroll
        for (int ks = 0; ks < 2; ++ks) {
            const uint32_t kb = ks * 32;
            uint32_t ah[4][4], al[4][4];
#pragma unroll
            for (int mt = 0; mt < 4; ++mt) {
                LDSM4(ah[mt], s + aAddr + mt * 16 * 80 + kb);
                LDSM4(al[mt], s + SA + aAddr + mt * 16 * 80 + kb);
            }
            uint32_t bh[4][2], bl[4][2];
#pragma unroll
            for (int ntp = 0; ntp < 2; ++ntp) {
                uint32_t t[4];
                LDSM4(t, s + bAddr + ntp * 16 * 80 + kb);
                bh[ntp*2][0] = t[0]; bh[ntp*2][1] = t[1];
                bh[ntp*2+1][0] = t[2]; bh[ntp*2+1][1] = t[3];
                LDSM4(t, s + SB + bAddr + ntp * 16 * 80 + kb);
                bl[ntp*2][0] = t[0]; bl[ntp*2][1] = t[1];
                bl[ntp*2+1][0] = t[2]; bl[ntp*2+1][1] = t[3];
            }
#pragma unroll
            for (int mt = 0; mt < 4; ++mt)
#pragma unroll
                for (int nt = 0; nt < 4; ++nt) {
                    MMA_BF16(acc[mt][nt], ah[mt], bh[nt]);
                    MMA_BF16(acc[mt][nt], ah[mt], bl[nt]);
                    MMA_BF16(acc[mt][nt], al[mt], bh[nt]);
                }
        }
        __syncthreads();
    }

#pragma unroll
    for (int mt = 0; mt < 4; ++mt) {
#pragma unroll
        for (int nt = 0; nt < 4; ++nt) {
            int row0 = m0 + wm0 + mt * 16 + (lane >> 2);
            int row1 = row0 + 8;
            int col = n0 + wn0 + nt * 8 + (lane & 3) * 2;
            float p0 = acc[mt][nt][0], p1 = acc[mt][nt][1];
            float p2 = acc[mt][nt][2], p3 = acc[mt][nt][3];
            if (EP == 0) {
                float b0 = bias[col], b1 = bias[col + 1];
                *(float2*)&C32[(long long)row0 * ldC + col] = make_float2(p0 + b0, p1 + b1);
                *(float2*)&C32[(long long)row1 * ldC + col] = make_float2(p2 + b0, p3 + b1);
            } else if (EP == 1) {
                float b0 = bias[col], b1 = bias[col + 1];
                float v0 = (p0 + b0) * scale, v1 = (p1 + b1) * scale;
                float v2 = (p2 + b0) * scale, v3 = (p3 + b1) * scale;
                uint32_t hp, lp;
                split_pack(v0, v1, hp, lp);
                *(uint32_t*)&Chi[(long long)row0 * ldC + col] = hp;
                *(uint32_t*)&Clo[(long long)row0 * ldC + col] = lp;
                split_pack(v2, v3, hp, lp);
                *(uint32_t*)&Chi[(long long)row1 * ldC + col] = hp;
                *(uint32_t*)&Clo[(long long)row1 * ldC + col] = lp;
            } else {  // EP == 3 : per-head transposed V: [b][h][d][s]
                float vals[4] = { p0, p1, p2, p3 };
                int rows[4] = { row0, row0, row1, row1 };
                int cols[4] = { col, col + 1, col, col + 1 };
#pragma unroll
                for (int e = 0; e < 4; ++e) {
                    float v = vals[e] + bias[cols[e]];
                    __nv_bfloat16 h, l; split2(v, h, l);
                    int bidx = rows[e] >> 11, sidx = rows[e] & 2047;
                    int hd = cols[e] >> 6, d = cols[e] & 63;
                    long long dst = ((long long)bidx * NHEAD + hd) * (DK * S_LEN)
                                  + (long long)d * S_LEN + sidx;
                    Chi[dst] = h; Clo[dst] = l;
                }
            }
        }
    }
}

// ===================== fused flash attention (bf16x3 HMMA) =====================
// Grid (16 qtiles, 16 heads, 2 batch). 256 threads = 8 warps; warp owns 16 q-rows.
// SMEM: Q hi/lo resident (pitch 144B), KV double-buffered:
//   K tile 128x64 (pitch 144B) hi/lo, V^T tile 64x128 (pitch 272B) hi/lo.
#define FA_QPITCH 144
#define FA_VPITCH 272
#define FA_KSZ   (128 * FA_QPITCH)          // 18432
#define FA_VSZ   (64 * FA_VPITCH)           // 17408
#define FA_OFF_STAGE (2 * FA_KSZ)           // 36864 : Q region size
#define FA_STAGE (2 * FA_KSZ + 2 * FA_VSZ)  // 71680
#define FA_SMEM  (FA_OFF_STAGE + 2 * FA_STAGE)  // 180224

__global__ __launch_bounds__(256, 1) void flash_attn(
    const __nv_bfloat16* __restrict__ qh_, const __nv_bfloat16* __restrict__ ql_,
    const __nv_bfloat16* __restrict__ kh_, const __nv_bfloat16* __restrict__ kl_,
    const __nv_bfloat16* __restrict__ vth_, const __nv_bfloat16* __restrict__ vtl_,
    __nv_bfloat16* __restrict__ oh_, __nv_bfloat16* __restrict__ ol_)
{
    extern __shared__ char smem[];
    const uint32_t sb = smem_u32(smem);
    const int tid = threadIdx.x;
    const int warp = tid >> 5, lane = tid & 31;
    const int qt = blockIdx.x, h = blockIdx.y, b = blockIdx.z;

    // global byte pointers
    const long long qrow0 = (long long)(b * S_LEN + qt * 128);
    const char* Qhg = (const char*)qh_ + (qrow0 * DMODEL + h * DK) * 2;
    const char* Qlg = (const char*)ql_ + (qrow0 * DMODEL + h * DK) * 2;
    const char* Khg = (const char*)kh_ + ((long long)b * S_LEN * DMODEL + h * DK) * 2;
    const char* Klg = (const char*)kl_ + ((long long)b * S_LEN * DMODEL + h * DK) * 2;
    const char* Vhg = (const char*)vth_ + ((long long)((b * NHEAD + h) * DK) * S_LEN) * 2;
    const char* Vlg = (const char*)vtl_ + ((long long)((b * NHEAD + h) * DK) * S_LEN) * 2;

    auto loadQ = [&]() {
#pragma unroll 4
        for (int u = tid; u < 1024; u += 256) {
            int r = u >> 3, seg = (u & 7) << 4;
            CP16(sb + r * FA_QPITCH + seg, Qhg + (long long)r * 2048 + seg);
            CP16(sb + FA_KSZ + r * FA_QPITCH + seg, Qlg + (long long)r * 2048 + seg);
        }
    };
    auto loadKV = [&](int kt, int buf) {
        const uint32_t s = sb + FA_OFF_STAGE + buf * FA_STAGE;
        const char* kh = Khg + (long long)kt * 128 * 2048;
        const char* kl = Klg + (long long)kt * 128 * 2048;
#pragma unroll 4
        for (int u = tid; u < 1024; u += 256) {
            int r = u >> 3, seg = (u & 7) << 4;
            CP16(s + r * FA_QPITCH + seg, kh + (long long)r * 2048 + seg);
            CP16(s + FA_KSZ + r * FA_QPITCH + seg, kl + (long long)r * 2048 + seg);
        }
        const char* vh = Vhg + kt * 256;
        const char* vl = Vlg + kt * 256;
#pragma unroll 4
        for (int u = tid; u < 1024; u += 256) {
            int r = u >> 4, seg = (u & 15) << 4;
            CP16(s + 2 * FA_KSZ + r * FA_VPITCH + seg, vh + (long long)r * 4096 + seg);
            CP16(s + 2 * FA_KSZ + FA_VSZ + r * FA_VPITCH + seg, vl + (long long)r * 4096 + seg);
        }
    };

    float accO[8][4];
#pragma unroll
    for (int i = 0; i < 8; ++i)
#pragma unroll
        for (int e = 0; e < 4; ++e) accO[i][e] = 0.f;
    float m0r = -1e30f, m1r = -1e30f, l0 = 0.f, l1 = 0.f;
    uint32_t qfh[4][4], qfl[4][4];

    loadQ(); loadKV(0, 0); CP_COMMIT();
    loadKV(1, 1); CP_COMMIT();

    const uint32_t qAddr = sb + (warp * 16 + (lane & 15)) * FA_QPITCH + (lane >> 4) * 16;
    const int g = lane >> 3;
    const uint32_t bRow = (g >> 1) * 8 + (lane & 7);
    const uint32_t bHalf = (g & 1) * 16;

    for (int kt = 0; kt < S_LEN / 128; ++kt) {
        CP_WAIT(1);
        __syncthreads();
        if (kt == 0) {
#pragma unroll
            for (int ks = 0; ks < 4; ++ks) {
                LDSM4(qfh[ks], qAddr + ks * 32);
                LDSM4(qfl[ks], qAddr + FA_KSZ + ks * 32);
            }
        }
        const uint32_t s = sb + FA_OFF_STAGE + (kt & 1) * FA_STAGE;

        // ---- S = Q @ K^T  (3 products) ----
        float accS[16][4];
#pragma unroll
        for (int i = 0; i < 16; ++i)
#pragma unroll
            for (int e = 0; e < 4; ++e) accS[i][e] = 0.f;
        const uint32_t kAddr = s + bRow * FA_QPITCH + bHalf;
#pragma unroll
        for (int ntp = 0; ntp < 8; ++ntp) {
#pragma unroll
            for (int ks = 0; ks < 4; ++ks) {
                uint32_t th[4], tl[4];
                LDSM4(th, kAddr + ntp * 16 * FA_QPITCH + ks * 32);
                LDSM4(tl, kAddr + FA_KSZ + ntp * 16 * FA_QPITCH + ks * 32);
                uint32_t bh0[2] = { th[0], th[1] }, bh1[2] = { th[2], th[3] };
                uint32_t bl0[2] = { tl[0], tl[1] }, bl1[2] = { tl[2], tl[3] };
                MMA_BF16(accS[2*ntp],   qfh[ks], bh0);
                MMA_BF16(accS[2*ntp],   qfh[ks], bl0);
                MMA_BF16(accS[2*ntp],   qfl[ks], bh0);
                MMA_BF16(accS[2*ntp+1], qfh[ks], bh1);
                MMA_BF16(accS[2*ntp+1], qfh[ks], bl1);
                MMA_BF16(accS[2*ntp+1], qfl[ks], bh1);
            }
        }

        // ---- online softmax (warp-local rows) ----
        float mx0 = -1e30f, mx1 = -1e30f;
#pragma unroll
        for (int nt = 0; nt < 16; ++nt) {
            mx0 = fmaxf(mx0, fmaxf(accS[nt][0], accS[nt][1]));
            mx1 = fmaxf(mx1, fmaxf(accS[nt][2], accS[nt][3]));
        }
        mx0 = fmaxf(mx0, __shfl_xor_sync(0xffffffffu, mx0, 1));
        mx0 = fmaxf(mx0, __shfl_xor_sync(0xffffffffu, mx0, 2));
        mx1 = fmaxf(mx1, __shfl_xor_sync(0xffffffffu, mx1, 1));
        mx1 = fmaxf(mx1, __shfl_xor_sync(0xffffffffu, mx1, 2));
        float mn0 = fmaxf(m0r, mx0), mn1 = fmaxf(m1r, mx1);
        float c0 = __expf(m0r - mn0), c1 = __expf(m1r - mn1);
        m0r = mn0; m1r = mn1;
        float s0 = 0.f, s1 = 0.f;
#pragma unroll
        for (int nt = 0; nt < 16; ++nt) {
            accS[nt][0] = __expf(accS[nt][0] - mn0);
            accS[nt][1] = __expf(accS[nt][1] - mn0);
            accS[nt][2] = __expf(accS[nt][2] - mn1);
            accS[nt][3] = __expf(accS[nt][3] - mn1);
            s0 += accS[nt][0] + accS[nt][1];
            s1 += accS[nt][2] + accS[nt][3];
        }
        s0 += __shfl_xor_sync(0xffffffffu, s0, 1);
        s0 += __shfl_xor_sync(0xffffffffu, s0, 2);
        s1 += __shfl_xor_sync(0xffffffffu, s1, 1);
        s1 += __shfl_xor_sync(0xffffffffu, s1, 2);
        l0 = l0 * c0 + s0;
        l1 = l1 * c1 + s1;
#pragma unroll
        for (int nt = 0; nt < 8; ++nt) {
            accO[nt][0] *= c0; accO[nt][1] *= c0;
            accO[nt][2] *= c1; accO[nt][3] *= c1;
        }

        // ---- O += P @ V  (P hi/lo built in registers; 3 products) ----
        const uint32_t vAddr = s + 2 * FA_KSZ + bRow * FA_VPITCH + bHalf;
#pragma unroll
        for (int kg = 0; kg < 8; ++kg) {
            uint32_t pah[4], pal[4];
            split_pack(accS[2*kg][0],   accS[2*kg][1],   pah[0], pal[0]);
            split_pack(accS[2*kg][2],   accS[2*kg][3],   pah[1], pal[1]);
            split_pack(accS[2*kg+1][0], accS[2*kg+1][1], pah[2], pal[2]);
            split_pack(accS[2*kg+1][2], accS[2*kg+1][3], pah[3], pal[3]);
#pragma unroll
            for (int ntp = 0; ntp < 4; ++ntp) {
                uint32_t th[4], tl[4];
                LDSM4(th, vAddr + ntp * 16 * FA_VPITCH + kg * 32);
                LDSM4(tl, vAddr + FA_VSZ + ntp * 16 * FA_VPITCH + kg * 32);
                uint32_t bh0[2] = { th[0], th[1] }, bh1[2] = { th[2], th[3] };
                uint32_t bl0[2] = { tl[0], tl[1] }, bl1[2] = { tl[2], tl[3] };
                MMA_BF16(accO[2*ntp],   pah, bh0);
                MMA_BF16(accO[2*ntp],   pah, bl0);
                MMA_BF16(accO[2*ntp],   pal, bh0);
                MMA_BF16(accO[2*ntp+1], pah, bh1);
                MMA_BF16(accO[2*ntp+1], pah, bl1);
                MMA_BF16(accO[2*ntp+1], pal, bh1);
            }
        }
        __syncthreads();
        if (kt + 2 < S_LEN / 128) loadKV(kt + 2, kt & 1);
        CP_COMMIT();
    }

    // ---- epilogue: divide by l, split hi/lo, write [tok][dmodel] ----
    const float inv0 = 1.0f / l0, inv1 = 1.0f / l1;
    const long long tok0 = qrow0 + warp * 16 + (lane >> 2);
    const int colb = h * DK + (lane & 3) * 2;
#pragma unroll
    for (int nt = 0; nt < 8; ++nt) {
        int col = colb + nt * 8;
        uint32_t hp, lp;
        split_pack(accO[nt][0] * inv0, accO[nt][1] * inv0, hp, lp);
        *(uint32_t*)&oh_[tok0 * DMODEL + col] = hp;
        *(uint32_t*)&ol_[tok0 * DMODEL + col] = lp;
        split_pack(accO[nt][2] * inv1, accO[nt][3] * inv1, hp, lp);
        *(uint32_t*)&oh_[(tok0 + 8) * DMODEL + col] = hp;
        *(uint32_t*)&ol_[(tok0 + 8) * DMODEL + col] = lp;
    }
}

// ===================== host =====================
static inline void* sym(const void* s) { void* p; cudaGetSymbolAddress(&p, s); return p; }

extern "C" void kernel_launch(void* const* d_in, const int* in_sizes, int n_in,
                              void* d_out, int out_size) {
    const float* v  = (const float*)d_in[0];
    const float* k  = (const float*)d_in[1];
    const float* q  = (const float*)d_in[2];
    const float* Wv = (const float*)d_in[3];
    const float* bv = (const float*)d_in[4];
    const float* Wk = (const float*)d_in[5];
    const float* bk = (const float*)d_in[6];
    const float* Wq = (const float*)d_in[7];
    const float* bq = (const float*)d_in[8];
    const float* Wo = (const float*)d_in[9];
    const float* bo = (const float*)d_in[10];

    __nv_bfloat16 *qh=(__nv_bfloat16*)sym(g_qh), *ql=(__nv_bfloat16*)sym(g_ql);
    __nv_bfloat16 *kh=(__nv_bfloat16*)sym(g_kh), *kl=(__nv_bfloat16*)sym(g_kl);
    __nv_bfloat16 *vh=(__nv_bfloat16*)sym(g_vh), *vl=(__nv_bfloat16*)sym(g_vl);
    __nv_bfloat16 *Wqh=(__nv_bfloat16*)sym(g_Wqh), *Wql=(__nv_bfloat16*)sym(g_Wql);
    __nv_bfloat16 *Wkh=(__nv_bfloat16*)sym(g_Wkh), *Wkl=(__nv_bfloat16*)sym(g_Wkl);
    __nv_bfloat16 *Wvh=(__nv_bfloat16*)sym(g_Wvh), *Wvl=(__nv_bfloat16*)sym(g_Wvl);
    __nv_bfloat16 *Woh=(__nv_bfloat16*)sym(g_Woh), *Wol=(__nv_bfloat16*)sym(g_Wol);
    __nv_bfloat16 *qph=(__nv_bfloat16*)sym(g_qph), *qpl=(__nv_bfloat16*)sym(g_qpl);
    __nv_bfloat16 *kph=(__nv_bfloat16*)sym(g_kph), *kpl=(__nv_bfloat16*)sym(g_kpl);
    __nv_bfloat16 *vTh=(__nv_bfloat16*)sym(g_vTh), *vTl=(__nv_bfloat16*)sym(g_vTl);
    __nv_bfloat16 *ath=(__nv_bfloat16*)sym(g_ath), *atl=(__nv_bfloat16*)sym(g_atl);

    const int SM_128 = 2 * (128 + 128) * 160;   // 81920
    cudaFuncSetAttribute(gemm_hmma<128,128,0>, cudaFuncAttributeMaxDynamicSharedMemorySize, SM_128);
    cudaFuncSetAttribute(gemm_hmma<128,128,1>, cudaFuncAttributeMaxDynamicSharedMemorySize, SM_128);
    cudaFuncSetAttribute(gemm_hmma<128,128,3>, cudaFuncAttributeMaxDynamicSharedMemorySize, SM_128);
    cudaFuncSetAttribute(flash_attn, cudaFuncAttributeMaxDynamicSharedMemorySize, FA_SMEM);

    // --- split conversions ---
    cvt_split<<<4096, 256>>>(q, qh, ql, NTOK * DMODEL);
    cvt_split<<<4096, 256>>>(k, kh, kl, NTOK * DMODEL);
    cvt_split<<<4096, 256>>>(v, vh, vl, NTOK * DMODEL);
    cvt_split<<<1024, 256>>>(Wq, Wqh, Wql, DMODEL * DMODEL);
    cvt_split<<<1024, 256>>>(Wk, Wkh, Wkl, DMODEL * DMODEL);
    cvt_split<<<1024, 256>>>(Wv, Wvh, Wvl, DMODEL * DMODEL);
    cvt_split<<<1024, 256>>>(Wo, Woh, Wol, DMODEL * DMODEL);

    // --- projections (fold 1/sqrt(DK)=0.125 into Q) ---
    dim3 gp(8, 32, 1);
    gemm_hmma<128,128,1><<<gp, 256, SM_128>>>(qh, ql, Wqh, Wql, 1024, 1024, 1024,
        nullptr, qph, qpl, bq, 0.125f, 1024);
    gemm_hmma<128,128,1><<<gp, 256, SM_128>>>(kh, kl, Wkh, Wkl, 1024, 1024, 1024,
        nullptr, kph, kpl, bk, 1.0f, 1024);
    gemm_hmma<128,128,3><<<gp, 256, SM_128>>>(vh, vl, Wvh, Wvl, 1024, 1024, 1024,
        nullptr, vTh, vTl, bv, 1.0f, 1024);

    // --- fused flash attention ---
    flash_attn<<<dim3(S_LEN / 128, NHEAD, 2), 256, FA_SMEM>>>(
        qph, qpl, kph, kpl, vTh, vTl, ath, atl);

    // --- final projection ---
    gemm_hmma<128,128,0><<<gp, 256, SM_128>>>(ath, atl, Woh, Wol, 1024, 1024, 1024,
        (float*)d_out, nullptr, nullptr, bo, 1.0f, 1024);
}

// round 5
// speedup vs baseline: 3.2810x; 1.1082x over previous
#include <cuda_runtime.h>
#include <cuda_bf16.h>
#include <cstdint>
#include <cstddef>

#define S_LEN  2048
#define DMODEL 1024
#define NHEAD  16
#define DK     64
#define NTOK   4096

// ===================== low-level helpers (base sm_103 target safe) =====================
__device__ __forceinline__ uint32_t smem_u32(const void* p) {
    uint32_t a;
    asm("{ .reg .u64 t; cvta.to.shared.u64 t, %1; cvt.u32.u64 %0, t; }" : "=r"(a) : "l"(p));
    return a;
}
#define CP16(dst, src) \
    asm volatile("cp.async.cg.shared.global [%0], [%1], 16;" :: "r"(dst), "l"(src))
#define CP_COMMIT() asm volatile("cp.async.commit_group;" ::: "memory")
#define CP_WAIT(n)  asm volatile("cp.async.wait_group %0;" :: "n"(n) : "memory")
#define LDSM4(d, addr) \
    asm volatile("ldmatrix.sync.aligned.m8n8.x4.shared.b16 {%0,%1,%2,%3}, [%4];" \
        : "=r"((d)[0]), "=r"((d)[1]), "=r"((d)[2]), "=r"((d)[3]) : "r"(addr))
#define MMA_BF16(c, a, b) \
    asm volatile("mma.sync.aligned.m16n8k16.row.col.f32.bf16.bf16.f32 " \
        "{%0,%1,%2,%3}, {%4,%5,%6,%7}, {%8,%9}, {%0,%1,%2,%3};" \
        : "+f"((c)[0]), "+f"((c)[1]), "+f"((c)[2]), "+f"((c)[3]) \
        : "r"((a)[0]), "r"((a)[1]), "r"((a)[2]), "r"((a)[3]), "r"((b)[0]), "r"((b)[1]))

__device__ __forceinline__ void split2(float v, __nv_bfloat16& h, __nv_bfloat16& l) {
    h = __float2bfloat16(v);
    l = __float2bfloat16(v - __bfloat162float(h));
}
__device__ __forceinline__ void split_pack(float x, float y, uint32_t& hp, uint32_t& lp) {
    __nv_bfloat16 hx, lx, hy, ly;
    split2(x, hx, lx); split2(y, hy, ly);
    __nv_bfloat162 h2(hx, hy), l2(lx, ly);
    hp = *reinterpret_cast<uint32_t*>(&h2);
    lp = *reinterpret_cast<uint32_t*>(&l2);
}

// ===================== scratch =====================
__device__ __nv_bfloat16 g_qh[NTOK*DMODEL], g_ql[NTOK*DMODEL];
__device__ __nv_bfloat16 g_kh[NTOK*DMODEL], g_kl[NTOK*DMODEL];
__device__ __nv_bfloat16 g_vh[NTOK*DMODEL], g_vl[NTOK*DMODEL];
__device__ __nv_bfloat16 g_Wqh[DMODEL*DMODEL], g_Wql[DMODEL*DMODEL];
__device__ __nv_bfloat16 g_Wkh[DMODEL*DMODEL], g_Wkl[DMODEL*DMODEL];
__device__ __nv_bfloat16 g_Wvh[DMODEL*DMODEL], g_Wvl[DMODEL*DMODEL];
__device__ __nv_bfloat16 g_Woh[DMODEL*DMODEL], g_Wol[DMODEL*DMODEL];
__device__ __nv_bfloat16 g_qph[NTOK*DMODEL], g_qpl[NTOK*DMODEL];
__device__ __nv_bfloat16 g_kph[NTOK*DMODEL], g_kpl[NTOK*DMODEL];
__device__ __nv_bfloat16 g_vTh[2*NHEAD*DK*S_LEN], g_vTl[2*NHEAD*DK*S_LEN];
__device__ __nv_bfloat16 g_ath[NTOK*DMODEL], g_atl[NTOK*DMODEL];

// ===================== merged fp32 -> (bf16 hi, bf16 lo) for all 7 tensors =====================
__global__ __launch_bounds__(256) void cvt_all(
    const float* __restrict__ q, const float* __restrict__ k, const float* __restrict__ v,
    const float* __restrict__ Wq, const float* __restrict__ Wk,
    const float* __restrict__ Wv, const float* __restrict__ Wo,
    __nv_bfloat16* qh, __nv_bfloat16* ql, __nv_bfloat16* kh, __nv_bfloat16* kl,
    __nv_bfloat16* vh, __nv_bfloat16* vl,
    __nv_bfloat16* Wqh, __nv_bfloat16* Wql, __nv_bfloat16* Wkh, __nv_bfloat16* Wkl,
    __nv_bfloat16* Wvh, __nv_bfloat16* Wvl, __nv_bfloat16* Woh, __nv_bfloat16* Wol)
{
    int bid = blockIdx.x;
    const float* src; __nv_bfloat16 *hi, *lo; int lb;
    if      (bid < 4096)  { src = q;  hi = qh;  lo = ql;  lb = bid; }
    else if (bid < 8192)  { src = k;  hi = kh;  lo = kl;  lb = bid - 4096; }
    else if (bid < 12288) { src = v;  hi = vh;  lo = vl;  lb = bid - 8192; }
    else if (bid < 13312) { src = Wq; hi = Wqh; lo = Wql; lb = bid - 12288; }
    else if (bid < 14336) { src = Wk; hi = Wkh; lo = Wkl; lb = bid - 13312; }
    else if (bid < 15360) { src = Wv; hi = Wvh; lo = Wvl; lb = bid - 14336; }
    else                  { src = Wo; hi = Woh; lo = Wol; lb = bid - 15360; }
    int i = (lb * 256 + threadIdx.x) * 4;
    float4 val = *(const float4*)(src + i);
    __nv_bfloat16 h0, h1, h2, h3, l0, l1, l2, l3;
    split2(val.x, h0, l0); split2(val.y, h1, l1);
    split2(val.z, h2, l2); split2(val.w, h3, l3);
    *(__nv_bfloat162*)(hi + i)     = __nv_bfloat162(h0, h1);
    *(__nv_bfloat162*)(hi + i + 2) = __nv_bfloat162(h2, h3);
    *(__nv_bfloat162*)(lo + i)     = __nv_bfloat162(l0, l1);
    *(__nv_bfloat162*)(lo + i + 2) = __nv_bfloat162(l2, l3);
}

// ===================== generic HMMA bf16x3 GEMM: 4 warps, 64x64 warp tile =====================
// EP: 0 fp32+bias | 1 bf16 hi/lo (+bias)*scale | 3 bf16 hi/lo V-transposed
template <int EP>
__global__ __launch_bounds__(128, 2) void gemm_hmma(
    const __nv_bfloat16* __restrict__ Ahi, const __nv_bfloat16* __restrict__ Alo,
    const __nv_bfloat16* __restrict__ Bhi, const __nv_bfloat16* __restrict__ Blo,
    int K, int ldA, int ldB,
    float* __restrict__ C32, __nv_bfloat16* __restrict__ Chi, __nv_bfloat16* __restrict__ Clo,
    const float* __restrict__ bias, float scale, int ldC)
{
    constexpr int BM = 128, BN = 128;
    constexpr int SA = BM * 80;
    constexpr int SB = BN * 80;
    constexpr int STAGE = 2 * SA + 2 * SB;
    extern __shared__ char smem[];
    const uint32_t sbase = smem_u32(smem);

    const int tid = threadIdx.x;
    const int warp = tid >> 5, lane = tid & 31;
    const int wm0 = (warp >> 1) * 64, wn0 = (warp & 1) * 64;
    const int m0 = blockIdx.y * BM;
    const int n0 = blockIdx.x * BN;

    const char* Ah = (const char*)Ahi;
    const char* Al = (const char*)Alo;
    const char* Bh = (const char*)Bhi;
    const char* Bl = (const char*)Blo;

    float acc[4][8][4];
#pragma unroll
    for (int i = 0; i < 4; ++i)
#pragma unroll
        for (int j = 0; j < 8; ++j)
#pragma unroll
            for (int e = 0; e < 4; ++e) acc[i][j][e] = 0.f;

    const int chunks = K >> 5;

    auto load_chunk = [&](int c, int buf) {
        const uint32_t s = sbase + buf * STAGE;
        const long long kB = (long long)c * 64;
#pragma unroll 4
        for (int u = tid; u < BM * 4; u += 128) {
            int r = u >> 2, cc = u & 3;
            long long go = ((long long)(m0 + r) * ldA) * 2 + kB + cc * 16;
            uint32_t so = r * 80 + cc * 16;
            CP16(s + so, Ah + go);
            CP16(s + SA + so, Al + go);
        }
#pragma unroll 4
        for (int u = tid; u < BN * 4; u += 128) {
            int r = u >> 2, cc = u & 3;
            long long go = ((long long)(n0 + r) * ldB) * 2 + kB + cc * 16;
            uint32_t so = r * 80 + cc * 16;
            CP16(s + 2 * SA + so, Bh + go);
            CP16(s + 2 * SA + SB + so, Bl + go);
        }
        CP_COMMIT();
    };

    const uint32_t aAddr = (wm0 + (lane & 15)) * 80 + (lane >> 4) * 16;
    const int g = lane >> 3;
    const uint32_t bAddr = 2 * SA + (wn0 + (g >> 1) * 8 + (lane & 7)) * 80 + (g & 1) * 16;

    load_chunk(0, 0);

    for (int c = 0; c < chunks; ++c) {
        const int buf = c & 1;
        if (c + 1 < chunks) {
            load_chunk(c + 1, buf ^ 1);
            CP_WAIT(1);
        } else {
            CP_WAIT(0);
        }
        __syncthreads();

        const uint32_t s = sbase + buf * STAGE;
#pragma unroll
        for (int ks = 0; ks < 2; ++ks) {
            const uint32_t kb = ks * 32;
            uint32_t ah[4][4], al[4][4];
#pragma unroll
            for (int mt = 0; mt < 4; ++mt) {
                LDSM4(ah[mt], s + aAddr + mt * 16 * 80 + kb);
                LDSM4(al[mt], s + SA + aAddr + mt * 16 * 80 + kb);
            }
            uint32_t bh[8][2], bl[8][2];
#pragma unroll
            for (int ntp = 0; ntp < 4; ++ntp) {
                uint32_t t[4];
                LDSM4(t, s + bAddr + ntp * 16 * 80 + kb);
                bh[ntp*2][0] = t[0]; bh[ntp*2][1] = t[1];
                bh[ntp*2+1][0] = t[2]; bh[ntp*2+1][1] = t[3];
                LDSM4(t, s + SB + bAddr + ntp * 16 * 80 + kb);
                bl[ntp*2][0] = t[0]; bl[ntp*2][1] = t[1];
                bl[ntp*2+1][0] = t[2]; bl[ntp*2+1][1] = t[3];
            }
#pragma unroll
            for (int mt = 0; mt < 4; ++mt)
#pragma unroll
                for (int nt = 0; nt < 8; ++nt) {
                    MMA_BF16(acc[mt][nt], ah[mt], bh[nt]);
                    MMA_BF16(acc[mt][nt], ah[mt], bl[nt]);
                    MMA_BF16(acc[mt][nt], al[mt], bh[nt]);
                }
        }
        __syncthreads();
    }

#pragma unroll
    for (int mt = 0; mt < 4; ++mt) {
#pragma unroll
        for (int nt = 0; nt < 8; ++nt) {
            int row0 = m0 + wm0 + mt * 16 + (lane >> 2);
            int row1 = row0 + 8;
            int col = n0 + wn0 + nt * 8 + (lane & 3) * 2;
            float p0 = acc[mt][nt][0], p1 = acc[mt][nt][1];
            float p2 = acc[mt][nt][2], p3 = acc[mt][nt][3];
            if (EP == 0) {
                float b0 = bias[col], b1 = bias[col + 1];
                *(float2*)&C32[(long long)row0 * ldC + col] = make_float2(p0 + b0, p1 + b1);
                *(float2*)&C32[(long long)row1 * ldC + col] = make_float2(p2 + b0, p3 + b1);
            } else if (EP == 1) {
                float b0 = bias[col], b1 = bias[col + 1];
                float v0 = (p0 + b0) * scale, v1 = (p1 + b1) * scale;
                float v2 = (p2 + b0) * scale, v3 = (p3 + b1) * scale;
                uint32_t hp, lp;
                split_pack(v0, v1, hp, lp);
                *(uint32_t*)&Chi[(long long)row0 * ldC + col] = hp;
                *(uint32_t*)&Clo[(long long)row0 * ldC + col] = lp;
                split_pack(v2, v3, hp, lp);
                *(uint32_t*)&Chi[(long long)row1 * ldC + col] = hp;
                *(uint32_t*)&Clo[(long long)row1 * ldC + col] = lp;
            } else {  // EP == 3 : per-head transposed V: [b][h][d][s]
                float vals[4] = { p0, p1, p2, p3 };
                int rows[4] = { row0, row0, row1, row1 };
                int cols[4] = { col, col + 1, col, col + 1 };
#pragma unroll
                for (int e = 0; e < 4; ++e) {
                    float vv = vals[e] + bias[cols[e]];
                    __nv_bfloat16 h, l; split2(vv, h, l);
                    int bidx = rows[e] >> 11, sidx = rows[e] & 2047;
                    int hd = cols[e] >> 6, d = cols[e] & 63;
                    long long dst = ((long long)bidx * NHEAD + hd) * (DK * S_LEN)
                                  + (long long)d * S_LEN + sidx;
                    Chi[dst] = h; Clo[dst] = l;
                }
            }
        }
    }
}

// ===================== fused flash attention v2 (bf16x3 HMMA) =====================
// Grid (8 qtiles, 16 heads, 2 batch). 256 threads = 8 warps; warp owns 32 q-rows.
// 128-key kt tiles, processed as 2 substeps of 64 keys (register budget).
#define FA_QPITCH 144
#define FA_VPITCH 272
#define FA_QSZ  (256 * FA_QPITCH)            // 36864 per hi/lo
#define FA_KSZ  (128 * FA_QPITCH)            // 18432 per hi/lo
#define FA_VSZ  (64 * FA_VPITCH)             // 17408 per hi/lo
#define FA_QREG (2 * FA_QSZ)                 // 73728
#define FA_STAGE (2 * FA_KSZ + 2 * FA_VSZ)   // 71680
#define FA_SMEM  (FA_QREG + 2 * FA_STAGE)    // 217088

__global__ __launch_bounds__(256, 1) void flash_attn(
    const __nv_bfloat16* __restrict__ qh_, const __nv_bfloat16* __restrict__ ql_,
    const __nv_bfloat16* __restrict__ kh_, const __nv_bfloat16* __restrict__ kl_,
    const __nv_bfloat16* __restrict__ vth_, const __nv_bfloat16* __restrict__ vtl_,
    __nv_bfloat16* __restrict__ oh_, __nv_bfloat16* __restrict__ ol_)
{
    extern __shared__ char smem[];
    const uint32_t sb = smem_u32(smem);
    const int tid = threadIdx.x;
    const int warp = tid >> 5, lane = tid & 31;
    const int qt = blockIdx.x, h = blockIdx.y, b = blockIdx.z;

    const long long qrow0 = (long long)(b * S_LEN + qt * 256);
    const char* Qhg = (const char*)qh_ + (qrow0 * DMODEL + h * DK) * 2;
    const char* Qlg = (const char*)ql_ + (qrow0 * DMODEL + h * DK) * 2;
    const char* Khg = (const char*)kh_ + ((long long)b * S_LEN * DMODEL + h * DK) * 2;
    const char* Klg = (const char*)kl_ + ((long long)b * S_LEN * DMODEL + h * DK) * 2;
    const char* Vhg = (const char*)vth_ + ((long long)((b * NHEAD + h) * DK) * S_LEN) * 2;
    const char* Vlg = (const char*)vtl_ + ((long long)((b * NHEAD + h) * DK) * S_LEN) * 2;

    auto loadQ = [&]() {
#pragma unroll 8
        for (int u = tid; u < 2048; u += 256) {
            int r = u >> 3, seg = (u & 7) << 4;
            CP16(sb + r * FA_QPITCH + seg, Qhg + (long long)r * 2048 + seg);
            CP16(sb + FA_QSZ + r * FA_QPITCH + seg, Qlg + (long long)r * 2048 + seg);
        }
    };
    auto loadKV = [&](int kt, int buf) {
        const uint32_t s = sb + FA_QREG + buf * FA_STAGE;
        const char* kh = Khg + (long long)kt * 128 * 2048;
        const char* kl = Klg + (long long)kt * 128 * 2048;
#pragma unroll 4
        for (int u = tid; u < 1024; u += 256) {
            int r = u >> 3, seg = (u & 7) << 4;
            CP16(s + r * FA_QPITCH + seg, kh + (long long)r * 2048 + seg);
            CP16(s + FA_KSZ + r * FA_QPITCH + seg, kl + (long long)r * 2048 + seg);
        }
        const char* vh = Vhg + kt * 256;
        const char* vl = Vlg + kt * 256;
#pragma unroll 4
        for (int u = tid; u < 1024; u += 256) {
            int r = u >> 4, seg = (u & 15) << 4;
            CP16(s + 2 * FA_KSZ + r * FA_VPITCH + seg, vh + (long long)r * 4096 + seg);
            CP16(s + 2 * FA_KSZ + FA_VSZ + r * FA_VPITCH + seg, vl + (long long)r * 4096 + seg);
        }
    };

    float accO[2][8][4];
#pragma unroll
    for (int mt = 0; mt < 2; ++mt)
#pragma unroll
        for (int i = 0; i < 8; ++i)
#pragma unroll
            for (int e = 0; e < 4; ++e) accO[mt][i][e] = 0.f;
    float fm[2][2] = {{-1e30f, -1e30f}, {-1e30f, -1e30f}};
    float fl[2][2] = {{0.f, 0.f}, {0.f, 0.f}};
    uint32_t qfh[2][4][4];   // resident Q-hi frags [mt][ks]

    loadQ(); loadKV(0, 0); CP_COMMIT();
    loadKV(1, 1); CP_COMMIT();

    const uint32_t qAddr = sb + (warp * 32 + (lane & 15)) * FA_QPITCH + (lane >> 4) * 16;
    const int g = lane >> 3;
    const uint32_t bRow = (g >> 1) * 8 + (lane & 7);
    const uint32_t bHalf = (g & 1) * 16;

    for (int kt = 0; kt < S_LEN / 128; ++kt) {
        CP_WAIT(1);
        __syncthreads();
        if (kt == 0) {
#pragma unroll
            for (int mt = 0; mt < 2; ++mt)
#pragma unroll
                for (int ks = 0; ks < 4; ++ks)
                    LDSM4(qfh[mt][ks], qAddr + mt * 16 * FA_QPITCH + ks * 32);
        }
        const uint32_t s = sb + FA_QREG + (kt & 1) * FA_STAGE;

#pragma unroll
        for (int ss = 0; ss < 2; ++ss) {
            // ---- S = Q @ K^T over 64 keys (3 products) ----
            float accS[2][8][4];
#pragma unroll
            for (int mt = 0; mt < 2; ++mt)
#pragma unroll
                for (int i = 0; i < 8; ++i)
#pragma unroll
                    for (int e = 0; e < 4; ++e) accS[mt][i][e] = 0.f;
#pragma unroll
            for (int ks = 0; ks < 4; ++ks) {
                uint32_t qfl0[4], qfl1[4];
                LDSM4(qfl0, qAddr + FA_QSZ + 0 * 16 * FA_QPITCH + ks * 32);
                LDSM4(qfl1, qAddr + FA_QSZ + 1 * 16 * FA_QPITCH + ks * 32);
#pragma unroll
                for (int ntp = 0; ntp < 4; ++ntp) {
                    const uint32_t kA = s + (ss * 64 + ntp * 16 + bRow) * FA_QPITCH + bHalf + ks * 32;
                    uint32_t th[4], tl[4];
                    LDSM4(th, kA);
                    LDSM4(tl, kA + FA_KSZ);
                    uint32_t bh0[2] = { th[0], th[1] }, bh1[2] = { th[2], th[3] };
                    uint32_t bl0[2] = { tl[0], tl[1] }, bl1[2] = { tl[2], tl[3] };
                    MMA_BF16(accS[0][2*ntp],   qfh[0][ks], bh0);
                    MMA_BF16(accS[0][2*ntp],   qfh[0][ks], bl0);
                    MMA_BF16(accS[0][2*ntp],   qfl0,       bh0);
                    MMA_BF16(accS[0][2*ntp+1], qfh[0][ks], bh1);
                    MMA_BF16(accS[0][2*ntp+1], qfh[0][ks], bl1);
                    MMA_BF16(accS[0][2*ntp+1], qfl0,       bh1);
                    MMA_BF16(accS[1][2*ntp],   qfh[1][ks], bh0);
                    MMA_BF16(accS[1][2*ntp],   qfh[1][ks], bl0);
                    MMA_BF16(accS[1][2*ntp],   qfl1,       bh0);
                    MMA_BF16(accS[1][2*ntp+1], qfh[1][ks], bh1);
                    MMA_BF16(accS[1][2*ntp+1], qfh[1][ks], bl1);
                    MMA_BF16(accS[1][2*ntp+1], qfl1,       bh1);
                }
            }

            // ---- online softmax (per mt, rows warp-local) ----
#pragma unroll
            for (int mt = 0; mt < 2; ++mt) {
                float mx0 = -1e30f, mx1 = -1e30f;
#pragma unroll
                for (int nt = 0; nt < 8; ++nt) {
                    mx0 = fmaxf(mx0, fmaxf(accS[mt][nt][0], accS[mt][nt][1]));
                    mx1 = fmaxf(mx1, fmaxf(accS[mt][nt][2], accS[mt][nt][3]));
                }
                mx0 = fmaxf(mx0, __shfl_xor_sync(0xffffffffu, mx0, 1));
                mx0 = fmaxf(mx0, __shfl_xor_sync(0xffffffffu, mx0, 2));
                mx1 = fmaxf(mx1, __shfl_xor_sync(0xffffffffu, mx1, 1));
                mx1 = fmaxf(mx1, __shfl_xor_sync(0xffffffffu, mx1, 2));
                float mn0 = fmaxf(fm[mt][0], mx0), mn1 = fmaxf(fm[mt][1], mx1);
                float c0 = __expf(fm[mt][0] - mn0), c1 = __expf(fm[mt][1] - mn1);
                fm[mt][0] = mn0; fm[mt][1] = mn1;
                float s0 = 0.f, s1 = 0.f;
#pragma unroll
                for (int nt = 0; nt < 8; ++nt) {
                    accS[mt][nt][0] = __expf(accS[mt][nt][0] - mn0);
                    accS[mt][nt][1] = __expf(accS[mt][nt][1] - mn0);
                    accS[mt][nt][2] = __expf(accS[mt][nt][2] - mn1);
                    accS[mt][nt][3] = __expf(accS[mt][nt][3] - mn1);
                    s0 += accS[mt][nt][0] + accS[mt][nt][1];
                    s1 += accS[mt][nt][2] + accS[mt][nt][3];
                }
                s0 += __shfl_xor_sync(0xffffffffu, s0, 1);
                s0 += __shfl_xor_sync(0xffffffffu, s0, 2);
                s1 += __shfl_xor_sync(0xffffffffu, s1, 1);
                s1 += __shfl_xor_sync(0xffffffffu, s1, 2);
                fl[mt][0] = fl[mt][0] * c0 + s0;
                fl[mt][1] = fl[mt][1] * c1 + s1;
#pragma unroll
                for (int nt = 0; nt < 8; ++nt) {
                    accO[mt][nt][0] *= c0; accO[mt][nt][1] *= c0;
                    accO[mt][nt][2] *= c1; accO[mt][nt][3] *= c1;
                }
            }

            // ---- O += P @ V over this 64-key substep ----
#pragma unroll
            for (int kg = 0; kg < 4; ++kg) {
                uint32_t pah[2][4], pal[2][4];
#pragma unroll
                for (int mt = 0; mt < 2; ++mt) {
                    split_pack(accS[mt][2*kg][0],   accS[mt][2*kg][1],   pah[mt][0], pal[mt][0]);
                    split_pack(accS[mt][2*kg][2],   accS[mt][2*kg][3],   pah[mt][1], pal[mt][1]);
                    split_pack(accS[mt][2*kg+1][0], accS[mt][2*kg+1][1], pah[mt][2], pal[mt][2]);
                    split_pack(accS[mt][2*kg+1][2], accS[mt][2*kg+1][3], pah[mt][3], pal[mt][3]);
                }
#pragma unroll
                for (int ntp = 0; ntp < 4; ++ntp) {
                    const uint32_t vA = s + 2 * FA_KSZ + (ntp * 16 + bRow) * FA_VPITCH
                                      + bHalf + ss * 128 + kg * 32;
                    uint32_t th[4], tl[4];
                    LDSM4(th, vA);
                    LDSM4(tl, vA + FA_VSZ);
                    uint32_t bh0[2] = { th[0], th[1] }, bh1[2] = { th[2], th[3] };
                    uint32_t bl0[2] = { tl[0], tl[1] }, bl1[2] = { tl[2], tl[3] };
#pragma unroll
                    for (int mt = 0; mt < 2; ++mt) {
                        MMA_BF16(accO[mt][2*ntp],   pah[mt], bh0);
                        MMA_BF16(accO[mt][2*ntp],   pah[mt], bl0);
                        MMA_BF16(accO[mt][2*ntp],   pal[mt], bh0);
                        MMA_BF16(accO[mt][2*ntp+1], pah[mt], bh1);
                        MMA_BF16(accO[mt][2*ntp+1], pah[mt], bl1);
                        MMA_BF16(accO[mt][2*ntp+1], pal[mt], bh1);
                    }
                }
            }
        }
        __syncthreads();
        if (kt + 2 < S_LEN / 128) loadKV(kt + 2, kt & 1);
        CP_COMMIT();
    }

    // ---- epilogue ----
#pragma unroll
    for (int mt = 0; mt < 2; ++mt) {
        const float inv0 = 1.0f / fl[mt][0], inv1 = 1.0f / fl[mt][1];
        const long long tok0 = qrow0 + warp * 32 + mt * 16 + (lane >> 2);
        const int colb = h * DK + (lane & 3) * 2;
#pragma unroll
        for (int nt = 0; nt < 8; ++nt) {
            int col = colb + nt * 8;
            uint32_t hp, lp;
            split_pack(accO[mt][nt][0] * inv0, accO[mt][nt][1] * inv0, hp, lp);
            *(uint32_t*)&oh_[tok0 * DMODEL + col] = hp;
            *(uint32_t*)&ol_[tok0 * DMODEL + col] = lp;
            split_pack(accO[mt][nt][2] * inv1, accO[mt][nt][3] * inv1, hp, lp);
            *(uint32_t*)&oh_[(tok0 + 8) * DMODEL + col] = hp;
            *(uint32_t*)&ol_[(tok0 + 8) * DMODEL + col] = lp;
        }
    }
}

// ===================== host =====================
static inline void* sym(const void* s) { void* p; cudaGetSymbolAddress(&p, s); return p; }

extern "C" void kernel_launch(void* const* d_in, const int* in_sizes, int n_in,
                              void* d_out, int out_size) {
    const float* v  = (const float*)d_in[0];
    const float* k  = (const float*)d_in[1];
    const float* q  = (const float*)d_in[2];
    const float* Wv = (const float*)d_in[3];
    const float* bv = (const float*)d_in[4];
    const float* Wk = (const float*)d_in[5];
    const float* bk = (const float*)d_in[6];
    const float* Wq = (const float*)d_in[7];
    const float* bq = (const float*)d_in[8];
    const float* Wo = (const float*)d_in[9];
    const float* bo = (const float*)d_in[10];

    __nv_bfloat16 *qh=(__nv_bfloat16*)sym(g_qh), *ql=(__nv_bfloat16*)sym(g_ql);
    __nv_bfloat16 *kh=(__nv_bfloat16*)sym(g_kh), *kl=(__nv_bfloat16*)sym(g_kl);
    __nv_bfloat16 *vh=(__nv_bfloat16*)sym(g_vh), *vl=(__nv_bfloat16*)sym(g_vl);
    __nv_bfloat16 *Wqh=(__nv_bfloat16*)sym(g_Wqh), *Wql=(__nv_bfloat16*)sym(g_Wql);
    __nv_bfloat16 *Wkh=(__nv_bfloat16*)sym(g_Wkh), *Wkl=(__nv_bfloat16*)sym(g_Wkl);
    __nv_bfloat16 *Wvh=(__nv_bfloat16*)sym(g_Wvh), *Wvl=(__nv_bfloat16*)sym(g_Wvl);
    __nv_bfloat16 *Woh=(__nv_bfloat16*)sym(g_Woh), *Wol=(__nv_bfloat16*)sym(g_Wol);
    __nv_bfloat16 *qph=(__nv_bfloat16*)sym(g_qph), *qpl=(__nv_bfloat16*)sym(g_qpl);
    __nv_bfloat16 *kph=(__nv_bfloat16*)sym(g_kph), *kpl=(__nv_bfloat16*)sym(g_kpl);
    __nv_bfloat16 *vTh=(__nv_bfloat16*)sym(g_vTh), *vTl=(__nv_bfloat16*)sym(g_vTl);
    __nv_bfloat16 *ath=(__nv_bfloat16*)sym(g_ath), *atl=(__nv_bfloat16*)sym(g_atl);

    const int SM_G = 2 * (128 + 128) * 160;   // 81920
    cudaFuncSetAttribute(gemm_hmma<0>, cudaFuncAttributeMaxDynamicSharedMemorySize, SM_G);
    cudaFuncSetAttribute(gemm_hmma<1>, cudaFuncAttributeMaxDynamicSharedMemorySize, SM_G);
    cudaFuncSetAttribute(gemm_hmma<3>, cudaFuncAttributeMaxDynamicSharedMemorySize, SM_G);
    cudaFuncSetAttribute(flash_attn, cudaFuncAttributeMaxDynamicSharedMemorySize, FA_SMEM);

    // --- launch 0: merged splits ---
    cvt_all<<<16384, 256>>>(q, k, v, Wq, Wk, Wv, Wo,
                            qh, ql, kh, kl, vh, vl,
                            Wqh, Wql, Wkh, Wkl, Wvh, Wvl, Woh, Wol);

    // --- launches 1-3: projections (fold 1/sqrt(DK)=0.125 into Q) ---
    dim3 gp(8, 32, 1);
    gemm_hmma<1><<<gp, 128, SM_G>>>(qh, ql, Wqh, Wql, 1024, 1024, 1024,
        nullptr, qph, qpl, bq, 0.125f, 1024);
    gemm_hmma<1><<<gp, 128, SM_G>>>(kh, kl, Wkh, Wkl, 1024, 1024, 1024,
        nullptr, kph, kpl, bk, 1.0f, 1024);
    gemm_hmma<3><<<gp, 128, SM_G>>>(vh, vl, Wvh, Wvl, 1024, 1024, 1024,
        nullptr, vTh, vTl, bv, 1.0f, 1024);

    // --- launch 4: fused flash attention ---
    flash_attn<<<dim3(S_LEN / 256, NHEAD, 2), 256, FA_SMEM>>>(
        qph, qpl, kph, kpl, vTh, vTl, ath, atl);

    // --- launch 5: final projection (profiled by ncu -s 5) ---
    gemm_hmma<0><<<gp, 128, SM_G>>>(ath, atl, Woh, Wol, 1024, 1024, 1024,
        (float*)d_out, nullptr, nullptr, bo, 1.0f, 1024);
}

// round 6
// speedup vs baseline: 3.4609x; 1.0548x over previous
#include <cuda_runtime.h>
#include <cuda_bf16.h>
#include <cstdint>
#include <cstddef>

#define S_LEN  2048
#define DMODEL 1024
#define NHEAD  16
#define DK     64
#define NTOK   4096

// ===================== low-level helpers (base sm_103 target safe) =====================
__device__ __forceinline__ uint32_t smem_u32(const void* p) {
    uint32_t a;
    asm("{ .reg .u64 t; cvta.to.shared.u64 t, %1; cvt.u32.u64 %0, t; }" : "=r"(a) : "l"(p));
    return a;
}
#define CP16(dst, src) \
    asm volatile("cp.async.cg.shared.global [%0], [%1], 16;" :: "r"(dst), "l"(src))
#define CP_COMMIT() asm volatile("cp.async.commit_group;" ::: "memory")
#define CP_WAIT(n)  asm volatile("cp.async.wait_group %0;" :: "n"(n) : "memory")
#define LDSM4(d, addr) \
    asm volatile("ldmatrix.sync.aligned.m8n8.x4.shared.b16 {%0,%1,%2,%3}, [%4];" \
        : "=r"((d)[0]), "=r"((d)[1]), "=r"((d)[2]), "=r"((d)[3]) : "r"(addr))
#define MMA_BF16(c, a, b) \
    asm volatile("mma.sync.aligned.m16n8k16.row.col.f32.bf16.bf16.f32 " \
        "{%0,%1,%2,%3}, {%4,%5,%6,%7}, {%8,%9}, {%0,%1,%2,%3};" \
        : "+f"((c)[0]), "+f"((c)[1]), "+f"((c)[2]), "+f"((c)[3]) \
        : "r"((a)[0]), "r"((a)[1]), "r"((a)[2]), "r"((a)[3]), "r"((b)[0]), "r"((b)[1]))

__device__ __forceinline__ void split2(float v, __nv_bfloat16& h, __nv_bfloat16& l) {
    h = __float2bfloat16(v);
    l = __float2bfloat16(v - __bfloat162float(h));
}
__device__ __forceinline__ void split_pack(float x, float y, uint32_t& hp, uint32_t& lp) {
    __nv_bfloat16 hx, lx, hy, ly;
    split2(x, hx, lx); split2(y, hy, ly);
    __nv_bfloat162 h2(hx, hy), l2(lx, ly);
    hp = *reinterpret_cast<uint32_t*>(&h2);
    lp = *reinterpret_cast<uint32_t*>(&l2);
}

// ===================== scratch =====================
__device__ __nv_bfloat16 g_qh[NTOK*DMODEL], g_ql[NTOK*DMODEL];
__device__ __nv_bfloat16 g_kh[NTOK*DMODEL], g_kl[NTOK*DMODEL];
__device__ __nv_bfloat16 g_vh[NTOK*DMODEL], g_vl[NTOK*DMODEL];
__device__ __nv_bfloat16 g_Wqh[DMODEL*DMODEL], g_Wql[DMODEL*DMODEL];
__device__ __nv_bfloat16 g_Wkh[DMODEL*DMODEL], g_Wkl[DMODEL*DMODEL];
__device__ __nv_bfloat16 g_Wvh[DMODEL*DMODEL], g_Wvl[DMODEL*DMODEL];
__device__ __nv_bfloat16 g_Woh[DMODEL*DMODEL], g_Wol[DMODEL*DMODEL];
__device__ __nv_bfloat16 g_qph[NTOK*DMODEL], g_qpl[NTOK*DMODEL];
__device__ __nv_bfloat16 g_kph[NTOK*DMODEL], g_kpl[NTOK*DMODEL];
__device__ __nv_bfloat16 g_vTh[2*NHEAD*DK*S_LEN], g_vTl[2*NHEAD*DK*S_LEN];
__device__ __nv_bfloat16 g_ath[NTOK*DMODEL], g_atl[NTOK*DMODEL];

// ===================== merged fp32 -> (bf16 hi, bf16 lo) =====================
__global__ __launch_bounds__(256) void cvt_all(
    const float* __restrict__ q, const float* __restrict__ k, const float* __restrict__ v,
    const float* __restrict__ Wq, const float* __restrict__ Wk,
    const float* __restrict__ Wv, const float* __restrict__ Wo,
    __nv_bfloat16* qh, __nv_bfloat16* ql, __nv_bfloat16* kh, __nv_bfloat16* kl,
    __nv_bfloat16* vh, __nv_bfloat16* vl,
    __nv_bfloat16* Wqh, __nv_bfloat16* Wql, __nv_bfloat16* Wkh, __nv_bfloat16* Wkl,
    __nv_bfloat16* Wvh, __nv_bfloat16* Wvl, __nv_bfloat16* Woh, __nv_bfloat16* Wol)
{
    int bid = blockIdx.x;
    const float* src; __nv_bfloat16 *hi, *lo; int lb;
    if      (bid < 4096)  { src = q;  hi = qh;  lo = ql;  lb = bid; }
    else if (bid < 8192)  { src = k;  hi = kh;  lo = kl;  lb = bid - 4096; }
    else if (bid < 12288) { src = v;  hi = vh;  lo = vl;  lb = bid - 8192; }
    else if (bid < 13312) { src = Wq; hi = Wqh; lo = Wql; lb = bid - 12288; }
    else if (bid < 14336) { src = Wk; hi = Wkh; lo = Wkl; lb = bid - 13312; }
    else if (bid < 15360) { src = Wv; hi = Wvh; lo = Wvl; lb = bid - 14336; }
    else                  { src = Wo; hi = Woh; lo = Wol; lb = bid - 15360; }
    int i = (lb * 256 + threadIdx.x) * 4;
    float4 val = *(const float4*)(src + i);
    __nv_bfloat16 h0, h1, h2, h3, l0, l1, l2, l3;
    split2(val.x, h0, l0); split2(val.y, h1, l1);
    split2(val.z, h2, l2); split2(val.w, h3, l3);
    *(__nv_bfloat162*)(hi + i)     = __nv_bfloat162(h0, h1);
    *(__nv_bfloat162*)(hi + i + 2) = __nv_bfloat162(h2, h3);
    *(__nv_bfloat162*)(lo + i)     = __nv_bfloat162(l0, l1);
    *(__nv_bfloat162*)(lo + i + 2) = __nv_bfloat162(l2, l3);
}

// ===================== HMMA bf16x3 GEMM body (K=1024, 128x128 tile, 4 warps 64x64) =====================
// ep: 0 fp32+bias | 1 bf16 hi/lo (+bias)*scale | 3 bf16 hi/lo V-transposed
__device__ __forceinline__ void gemm_body(
    int ep,
    const char* Ah, const char* Al, const char* Bh, const char* Bl,
    float* C32, __nv_bfloat16* Chi, __nv_bfloat16* Clo,
    const float* bias, float scale, char* smem)
{
    constexpr int SA = 128 * 80;
    constexpr int SB = 128 * 80;
    constexpr int STAGE = 2 * SA + 2 * SB;
    const uint32_t sbase = smem_u32(smem);
    const int ldA = DMODEL, ldB = DMODEL, ldC = DMODEL;

    const int tid = threadIdx.x;
    const int warp = tid >> 5, lane = tid & 31;
    const int wm0 = (warp >> 1) * 64, wn0 = (warp & 1) * 64;
    const int m0 = blockIdx.y * 128;
    const int n0 = blockIdx.x * 128;

    float acc[4][8][4];
#pragma unroll
    for (int i = 0; i < 4; ++i)
#pragma unroll
        for (int j = 0; j < 8; ++j)
#pragma unroll
            for (int e = 0; e < 4; ++e) acc[i][j][e] = 0.f;

    auto load_chunk = [&](int c, int buf) {
        const uint32_t s = sbase + buf * STAGE;
        const long long kB = (long long)c * 64;
#pragma unroll 4
        for (int u = tid; u < 512; u += 128) {
            int r = u >> 2, cc = u & 3;
            long long go = ((long long)(m0 + r) * ldA) * 2 + kB + cc * 16;
            uint32_t so = r * 80 + cc * 16;
            CP16(s + so, Ah + go);
            CP16(s + SA + so, Al + go);
        }
#pragma unroll 4
        for (int u = tid; u < 512; u += 128) {
            int r = u >> 2, cc = u & 3;
            long long go = ((long long)(n0 + r) * ldB) * 2 + kB + cc * 16;
            uint32_t so = r * 80 + cc * 16;
            CP16(s + 2 * SA + so, Bh + go);
            CP16(s + 2 * SA + SB + so, Bl + go);
        }
        CP_COMMIT();
    };

    const uint32_t aAddr = (wm0 + (lane & 15)) * 80 + (lane >> 4) * 16;
    const int g = lane >> 3;
    const uint32_t bAddr = 2 * SA + (wn0 + (g >> 1) * 8 + (lane & 7)) * 80 + (g & 1) * 16;

    load_chunk(0, 0);

    const int chunks = 32;
    for (int c = 0; c < chunks; ++c) {
        const int buf = c & 1;
        if (c + 1 < chunks) {
            load_chunk(c + 1, buf ^ 1);
            CP_WAIT(1);
        } else {
            CP_WAIT(0);
        }
        __syncthreads();

        const uint32_t s = sbase + buf * STAGE;
#pragma unroll
        for (int ks = 0; ks < 2; ++ks) {
            const uint32_t kb = ks * 32;
            uint32_t ah[4][4], al[4][4];
#pragma unroll
            for (int mt = 0; mt < 4; ++mt) {
                LDSM4(ah[mt], s + aAddr + mt * 16 * 80 + kb);
                LDSM4(al[mt], s + SA + aAddr + mt * 16 * 80 + kb);
            }
            uint32_t bh[8][2], bl[8][2];
#pragma unroll
            for (int ntp = 0; ntp < 4; ++ntp) {
                uint32_t t[4];
                LDSM4(t, s + bAddr + ntp * 16 * 80 + kb);
                bh[ntp*2][0] = t[0]; bh[ntp*2][1] = t[1];
                bh[ntp*2+1][0] = t[2]; bh[ntp*2+1][1] = t[3];
                LDSM4(t, s + SB + bAddr + ntp * 16 * 80 + kb);
                bl[ntp*2][0] = t[0]; bl[ntp*2][1] = t[1];
                bl[ntp*2+1][0] = t[2]; bl[ntp*2+1][1] = t[3];
            }
#pragma unroll
            for (int mt = 0; mt < 4; ++mt)
#pragma unroll
                for (int nt = 0; nt < 8; ++nt) {
                    MMA_BF16(acc[mt][nt], ah[mt], bh[nt]);
                    MMA_BF16(acc[mt][nt], ah[mt], bl[nt]);
                    MMA_BF16(acc[mt][nt], al[mt], bh[nt]);
                }
        }
        __syncthreads();
    }

#pragma unroll
    for (int mt = 0; mt < 4; ++mt) {
#pragma unroll
        for (int nt = 0; nt < 8; ++nt) {
            int row0 = m0 + wm0 + mt * 16 + (lane >> 2);
            int row1 = row0 + 8;
            int col = n0 + wn0 + nt * 8 + (lane & 3) * 2;
            float p0 = acc[mt][nt][0], p1 = acc[mt][nt][1];
            float p2 = acc[mt][nt][2], p3 = acc[mt][nt][3];
            if (ep == 0) {
                float b0 = bias[col], b1 = bias[col + 1];
                *(float2*)&C32[(long long)row0 * ldC + col] = make_float2(p0 + b0, p1 + b1);
                *(float2*)&C32[(long long)row1 * ldC + col] = make_float2(p2 + b0, p3 + b1);
            } else if (ep == 1) {
                float b0 = bias[col], b1 = bias[col + 1];
                float v0 = (p0 + b0) * scale, v1 = (p1 + b1) * scale;
                float v2 = (p2 + b0) * scale, v3 = (p3 + b1) * scale;
                uint32_t hp, lp;
                split_pack(v0, v1, hp, lp);
                *(uint32_t*)&Chi[(long long)row0 * ldC + col] = hp;
                *(uint32_t*)&Clo[(long long)row0 * ldC + col] = lp;
                split_pack(v2, v3, hp, lp);
                *(uint32_t*)&Chi[(long long)row1 * ldC + col] = hp;
                *(uint32_t*)&Clo[(long long)row1 * ldC + col] = lp;
            } else {  // ep == 3 : per-head transposed V: [b][h][d][s]
                float vals[4] = { p0, p1, p2, p3 };
                int rows[4] = { row0, row0, row1, row1 };
                int cols[4] = { col, col + 1, col, col + 1 };
#pragma unroll
                for (int e = 0; e < 4; ++e) {
                    float vv = vals[e] + bias[cols[e]];
                    __nv_bfloat16 h, l; split2(vv, h, l);
                    int bidx = rows[e] >> 11, sidx = rows[e] & 2047;
                    int hd = cols[e] >> 6, d = cols[e] & 63;
                    long long dst = ((long long)bidx * NHEAD + hd) * (DK * S_LEN)
                                  + (long long)d * S_LEN + sidx;
                    Chi[dst] = h; Clo[dst] = l;
                }
            }
        }
    }
}

// merged Q/K/V projections: blockIdx.z selects operands
__global__ __launch_bounds__(128, 2) void proj_qkv(
    const __nv_bfloat16* qh, const __nv_bfloat16* ql,
    const __nv_bfloat16* kh, const __nv_bfloat16* kl,
    const __nv_bfloat16* vh, const __nv_bfloat16* vl,
    const __nv_bfloat16* Wqh, const __nv_bfloat16* Wql,
    const __nv_bfloat16* Wkh, const __nv_bfloat16* Wkl,
    const __nv_bfloat16* Wvh, const __nv_bfloat16* Wvl,
    const float* bq, const float* bk, const float* bv,
    __nv_bfloat16* qph, __nv_bfloat16* qpl,
    __nv_bfloat16* kph, __nv_bfloat16* kpl,
    __nv_bfloat16* vTh, __nv_bfloat16* vTl)
{
    extern __shared__ char smem[];
    int z = blockIdx.z;
    if (z == 0) {
        gemm_body(1, (const char*)qh, (const char*)ql, (const char*)Wqh, (const char*)Wql,
                  nullptr, qph, qpl, bq, 0.125f, smem);
    } else if (z == 1) {
        gemm_body(1, (const char*)kh, (const char*)kl, (const char*)Wkh, (const char*)Wkl,
                  nullptr, kph, kpl, bk, 1.0f, smem);
    } else {
        gemm_body(3, (const char*)vh, (const char*)vl, (const char*)Wvh, (const char*)Wvl,
                  nullptr, vTh, vTl, bv, 1.0f, smem);
    }
}

// final projection (fp32 out + bias)
__global__ __launch_bounds__(128, 2) void proj_out(
    const __nv_bfloat16* ath, const __nv_bfloat16* atl,
    const __nv_bfloat16* Woh, const __nv_bfloat16* Wol,
    const float* bo, float* out)
{
    extern __shared__ char smem[];
    gemm_body(0, (const char*)ath, (const char*)atl, (const char*)Woh, (const char*)Wol,
              out, nullptr, nullptr, bo, 1.0f, smem);
}

// ===================== fused flash attention v3 (4 warps, 64-key stages, 2 CTA/SM) =====================
#define FB_PITCH 144
#define FB_QSZ  (128 * FB_PITCH)             // 18432 per hi/lo
#define FB_KSZ  (64 * FB_PITCH)              // 9216 per hi/lo
#define FB_VSZ  (64 * FB_PITCH)              // 9216 per hi/lo
#define FB_QREG (2 * FB_QSZ)                 // 36864
#define FB_STAGE (2 * FB_KSZ + 2 * FB_VSZ)   // 36864
#define FB_SMEM  (FB_QREG + 2 * FB_STAGE)    // 110592

__global__ __launch_bounds__(128, 2) void flash_attn(
    const __nv_bfloat16* __restrict__ qh_, const __nv_bfloat16* __restrict__ ql_,
    const __nv_bfloat16* __restrict__ kh_, const __nv_bfloat16* __restrict__ kl_,
    const __nv_bfloat16* __restrict__ vth_, const __nv_bfloat16* __restrict__ vtl_,
    __nv_bfloat16* __restrict__ oh_, __nv_bfloat16* __restrict__ ol_)
{
    extern __shared__ char smem[];
    const uint32_t sb = smem_u32(smem);
    const int tid = threadIdx.x;
    const int warp = tid >> 5, lane = tid & 31;
    const int qt = blockIdx.x, h = blockIdx.y, b = blockIdx.z;

    const long long qrow0 = (long long)(b * S_LEN + qt * 128);
    const char* Qhg = (const char*)qh_ + (qrow0 * DMODEL + h * DK) * 2;
    const char* Qlg = (const char*)ql_ + (qrow0 * DMODEL + h * DK) * 2;
    const char* Khg = (const char*)kh_ + ((long long)b * S_LEN * DMODEL + h * DK) * 2;
    const char* Klg = (const char*)kl_ + ((long long)b * S_LEN * DMODEL + h * DK) * 2;
    const char* Vhg = (const char*)vth_ + ((long long)((b * NHEAD + h) * DK) * S_LEN) * 2;
    const char* Vlg = (const char*)vtl_ + ((long long)((b * NHEAD + h) * DK) * S_LEN) * 2;

    auto loadQ = [&]() {
#pragma unroll 8
        for (int u = tid; u < 1024; u += 128) {
            int r = u >> 3, seg = (u & 7) << 4;
            CP16(sb + r * FB_PITCH + seg, Qhg + (long long)r * 2048 + seg);
            CP16(sb + FB_QSZ + r * FB_PITCH + seg, Qlg + (long long)r * 2048 + seg);
        }
    };
    auto loadKV = [&](int kt, int buf) {   // kt indexes 64-key tiles
        const uint32_t s = sb + FB_QREG + buf * FB_STAGE;
        const char* kh = Khg + (long long)kt * 64 * 2048;
        const char* kl = Klg + (long long)kt * 64 * 2048;
#pragma unroll 4
        for (int u = tid; u < 512; u += 128) {
            int r = u >> 3, seg = (u & 7) << 4;
            CP16(s + r * FB_PITCH + seg, kh + (long long)r * 2048 + seg);
            CP16(s + FB_KSZ + r * FB_PITCH + seg, kl + (long long)r * 2048 + seg);
        }
        const char* vh = Vhg + kt * 128;
        const char* vl = Vlg + kt * 128;
#pragma unroll 4
        for (int u = tid; u < 512; u += 128) {
            int r = u >> 3, seg = (u & 7) << 4;
            CP16(s + 2 * FB_KSZ + r * FB_PITCH + seg, vh + (long long)r * 4096 + seg);
            CP16(s + 2 * FB_KSZ + FB_VSZ + r * FB_PITCH + seg, vl + (long long)r * 4096 + seg);
        }
    };

    float accO[2][8][4];
#pragma unroll
    for (int mt = 0; mt < 2; ++mt)
#pragma unroll
        for (int i = 0; i < 8; ++i)
#pragma unroll
            for (int e = 0; e < 4; ++e) accO[mt][i][e] = 0.f;
    float fm[2][2] = {{-1e30f, -1e30f}, {-1e30f, -1e30f}};
    float fl[2][2] = {{0.f, 0.f}, {0.f, 0.f}};
    uint32_t qfh[2][4][4];   // resident Q-hi frags

    loadQ(); loadKV(0, 0); CP_COMMIT();
    loadKV(1, 1); CP_COMMIT();

    const uint32_t qAddr = sb + (warp * 32 + (lane & 15)) * FB_PITCH + (lane >> 4) * 16;
    const int g = lane >> 3;
    const uint32_t bRow = (g >> 1) * 8 + (lane & 7);
    const uint32_t bHalf = (g & 1) * 16;

    const int NT64 = S_LEN / 64;   // 32
    for (int kt = 0; kt < NT64; ++kt) {
        CP_WAIT(1);
        __syncthreads();
        if (kt == 0) {
#pragma unroll
            for (int mt = 0; mt < 2; ++mt)
#pragma unroll
                for (int ks = 0; ks < 4; ++ks)
                    LDSM4(qfh[mt][ks], qAddr + mt * 16 * FB_PITCH + ks * 32);
        }
        const uint32_t s = sb + FB_QREG + (kt & 1) * FB_STAGE;

        // ---- S = Q @ K^T over 64 keys (3 products) ----
        float accS[2][8][4];
#pragma unroll
        for (int mt = 0; mt < 2; ++mt)
#pragma unroll
            for (int i = 0; i < 8; ++i)
#pragma unroll
                for (int e = 0; e < 4; ++e) accS[mt][i][e] = 0.f;
#pragma unroll
        for (int ks = 0; ks < 4; ++ks) {
            uint32_t qfl0[4], qfl1[4];
            LDSM4(qfl0, qAddr + FB_QSZ + 0 * 16 * FB_PITCH + ks * 32);
            LDSM4(qfl1, qAddr + FB_QSZ + 1 * 16 * FB_PITCH + ks * 32);
#pragma unroll
            for (int ntp = 0; ntp < 4; ++ntp) {
                const uint32_t kA = s + (ntp * 16 + bRow) * FB_PITCH + bHalf + ks * 32;
                uint32_t th[4], tl[4];
                LDSM4(th, kA);
                LDSM4(tl, kA + FB_KSZ);
                uint32_t bh0[2] = { th[0], th[1] }, bh1[2] = { th[2], th[3] };
                uint32_t bl0[2] = { tl[0], tl[1] }, bl1[2] = { tl[2], tl[3] };
                MMA_BF16(accS[0][2*ntp],   qfh[0][ks], bh0);
                MMA_BF16(accS[0][2*ntp],   qfh[0][ks], bl0);
                MMA_BF16(accS[0][2*ntp],   qfl0,       bh0);
                MMA_BF16(accS[0][2*ntp+1], qfh[0][ks], bh1);
                MMA_BF16(accS[0][2*ntp+1], qfh[0][ks], bl1);
                MMA_BF16(accS[0][2*ntp+1], qfl0,       bh1);
                MMA_BF16(accS[1][2*ntp],   qfh[1][ks], bh0);
                MMA_BF16(accS[1][2*ntp],   qfh[1][ks], bl0);
                MMA_BF16(accS[1][2*ntp],   qfl1,       bh0);
                MMA_BF16(accS[1][2*ntp+1], qfh[1][ks], bh1);
                MMA_BF16(accS[1][2*ntp+1], qfh[1][ks], bl1);
                MMA_BF16(accS[1][2*ntp+1], qfl1,       bh1);
            }
        }

        // ---- online softmax ----
#pragma unroll
        for (int mt = 0; mt < 2; ++mt) {
            float mx0 = -1e30f, mx1 = -1e30f;
#pragma unroll
            for (int nt = 0; nt < 8; ++nt) {
                mx0 = fmaxf(mx0, fmaxf(accS[mt][nt][0], accS[mt][nt][1]));
                mx1 = fmaxf(mx1, fmaxf(accS[mt][nt][2], accS[mt][nt][3]));
            }
            mx0 = fmaxf(mx0, __shfl_xor_sync(0xffffffffu, mx0, 1));
            mx0 = fmaxf(mx0, __shfl_xor_sync(0xffffffffu, mx0, 2));
            mx1 = fmaxf(mx1, __shfl_xor_sync(0xffffffffu, mx1, 1));
            mx1 = fmaxf(mx1, __shfl_xor_sync(0xffffffffu, mx1, 2));
            float mn0 = fmaxf(fm[mt][0], mx0), mn1 = fmaxf(fm[mt][1], mx1);
            float c0 = __expf(fm[mt][0] - mn0), c1 = __expf(fm[mt][1] - mn1);
            fm[mt][0] = mn0; fm[mt][1] = mn1;
            float s0 = 0.f, s1 = 0.f;
#pragma unroll
            for (int nt = 0; nt < 8; ++nt) {
                accS[mt][nt][0] = __expf(accS[mt][nt][0] - mn0);
                accS[mt][nt][1] = __expf(accS[mt][nt][1] - mn0);
                accS[mt][nt][2] = __expf(accS[mt][nt][2] - mn1);
                accS[mt][nt][3] = __expf(accS[mt][nt][3] - mn1);
                s0 += accS[mt][nt][0] + accS[mt][nt][1];
                s1 += accS[mt][nt][2] + accS[mt][nt][3];
            }
            s0 += __shfl_xor_sync(0xffffffffu, s0, 1);
            s0 += __shfl_xor_sync(0xffffffffu, s0, 2);
            s1 += __shfl_xor_sync(0xffffffffu, s1, 1);
            s1 += __shfl_xor_sync(0xffffffffu, s1, 2);
            fl[mt][0] = fl[mt][0] * c0 + s0;
            fl[mt][1] = fl[mt][1] * c1 + s1;
#pragma unroll
            for (int nt = 0; nt < 8; ++nt) {
                accO[mt][nt][0] *= c0; accO[mt][nt][1] *= c0;
                accO[mt][nt][2] *= c1; accO[mt][nt][3] *= c1;
            }
        }

        // ---- O += P @ V ----
#pragma unroll
        for (int kg = 0; kg < 4; ++kg) {
            uint32_t pah[2][4], pal[2][4];
#pragma unroll
            for (int mt = 0; mt < 2; ++mt) {
                split_pack(accS[mt][2*kg][0],   accS[mt][2*kg][1],   pah[mt][0], pal[mt][0]);
                split_pack(accS[mt][2*kg][2],   accS[mt][2*kg][3],   pah[mt][1], pal[mt][1]);
                split_pack(accS[mt][2*kg+1][0], accS[mt][2*kg+1][1], pah[mt][2], pal[mt][2]);
                split_pack(accS[mt][2*kg+1][2], accS[mt][2*kg+1][3], pah[mt][3], pal[mt][3]);
            }
#pragma unroll
            for (int ntp = 0; ntp < 4; ++ntp) {
                const uint32_t vA = s + 2 * FB_KSZ + (ntp * 16 + bRow) * FB_PITCH
                                  + bHalf + kg * 32;
                uint32_t th[4], tl[4];
                LDSM4(th, vA);
                LDSM4(tl, vA + FB_VSZ);
                uint32_t bh0[2] = { th[0], th[1] }, bh1[2] = { th[2], th[3] };
                uint32_t bl0[2] = { tl[0], tl[1] }, bl1[2] = { tl[2], tl[3] };
#pragma unroll
                for (int mt = 0; mt < 2; ++mt) {
                    MMA_BF16(accO[mt][2*ntp],   pah[mt], bh0);
                    MMA_BF16(accO[mt][2*ntp],   pah[mt], bl0);
                    MMA_BF16(accO[mt][2*ntp],   pal[mt], bh0);
                    MMA_BF16(accO[mt][2*ntp+1], pah[mt], bh1);
                    MMA_BF16(accO[mt][2*ntp+1], pah[mt], bl1);
                    MMA_BF16(accO[mt][2*ntp+1], pal[mt], bh1);
                }
            }
        }
        __syncthreads();
        if (kt + 2 < NT64) loadKV(kt + 2, kt & 1);
        CP_COMMIT();
    }

    // ---- epilogue ----
#pragma unroll
    for (int mt = 0; mt < 2; ++mt) {
        const float inv0 = 1.0f / fl[mt][0], inv1 = 1.0f / fl[mt][1];
        const long long tok0 = qrow0 + warp * 32 + mt * 16 + (lane >> 2);
        const int colb = h * DK + (lane & 3) * 2;
#pragma unroll
        for (int nt = 0; nt < 8; ++nt) {
            int col = colb + nt * 8;
            uint32_t hp, lp;
            split_pack(accO[mt][nt][0] * inv0, accO[mt][nt][1] * inv0, hp, lp);
            *(uint32_t*)&oh_[tok0 * DMODEL + col] = hp;
            *(uint32_t*)&ol_[tok0 * DMODEL + col] = lp;
            split_pack(accO[mt][nt][2] * inv1, accO[mt][nt][3] * inv1, hp, lp);
            *(uint32_t*)&oh_[(tok0 + 8) * DMODEL + col] = hp;
            *(uint32_t*)&ol_[(tok0 + 8) * DMODEL + col] = lp;
        }
    }
}

// ===================== host =====================
static inline void* sym(const void* s) { void* p; cudaGetSymbolAddress(&p, s); return p; }

extern "C" void kernel_launch(void* const* d_in, const int* in_sizes, int n_in,
                              void* d_out, int out_size) {
    const float* v  = (const float*)d_in[0];
    const float* k  = (const float*)d_in[1];
    const float* q  = (const float*)d_in[2];
    const float* Wv = (const float*)d_in[3];
    const float* bv = (const float*)d_in[4];
    const float* Wk = (const float*)d_in[5];
    const float* bk = (const float*)d_in[6];
    const float* Wq = (const float*)d_in[7];
    const float* bq = (const float*)d_in[8];
    const float* Wo = (const float*)d_in[9];
    const float* bo = (const float*)d_in[10];

    __nv_bfloat16 *qh=(__nv_bfloat16*)sym(g_qh), *ql=(__nv_bfloat16*)sym(g_ql);
    __nv_bfloat16 *kh=(__nv_bfloat16*)sym(g_kh), *kl=(__nv_bfloat16*)sym(g_kl);
    __nv_bfloat16 *vh=(__nv_bfloat16*)sym(g_vh), *vl=(__nv_bfloat16*)sym(g_vl);
    __nv_bfloat16 *Wqh=(__nv_bfloat16*)sym(g_Wqh), *Wql=(__nv_bfloat16*)sym(g_Wql);
    __nv_bfloat16 *Wkh=(__nv_bfloat16*)sym(g_Wkh), *Wkl=(__nv_bfloat16*)sym(g_Wkl);
    __nv_bfloat16 *Wvh=(__nv_bfloat16*)sym(g_Wvh), *Wvl=(__nv_bfloat16*)sym(g_Wvl);
    __nv_bfloat16 *Woh=(__nv_bfloat16*)sym(g_Woh), *Wol=(__nv_bfloat16*)sym(g_Wol);
    __nv_bfloat16 *qph=(__nv_bfloat16*)sym(g_qph), *qpl=(__nv_bfloat16*)sym(g_qpl);
    __nv_bfloat16 *kph=(__nv_bfloat16*)sym(g_kph), *kpl=(__nv_bfloat16*)sym(g_kpl);
    __nv_bfloat16 *vTh=(__nv_bfloat16*)sym(g_vTh), *vTl=(__nv_bfloat16*)sym(g_vTl);
    __nv_bfloat16 *ath=(__nv_bfloat16*)sym(g_ath), *atl=(__nv_bfloat16*)sym(g_atl);

    const int SM_G = 2 * (128 + 128) * 160;   // 81920
    cudaFuncSetAttribute(proj_qkv, cudaFuncAttributeMaxDynamicSharedMemorySize, SM_G);
    cudaFuncSetAttribute(proj_out, cudaFuncAttributeMaxDynamicSharedMemorySize, SM_G);
    cudaFuncSetAttribute(flash_attn, cudaFuncAttributeMaxDynamicSharedMemorySize, FB_SMEM);

    // launch 0: merged hi/lo splits
    cvt_all<<<16384, 256>>>(q, k, v, Wq, Wk, Wv, Wo,
                            qh, ql, kh, kl, vh, vl,
                            Wqh, Wql, Wkh, Wkl, Wvh, Wvl, Woh, Wol);

    // launch 1: merged Q/K/V projections
    proj_qkv<<<dim3(8, 32, 3), 128, SM_G>>>(
        qh, ql, kh, kl, vh, vl,
        Wqh, Wql, Wkh, Wkl, Wvh, Wvl,
        bq, bk, bv, qph, qpl, kph, kpl, vTh, vTl);

    // launch 2: fused flash attention (2 CTA/SM)
    flash_attn<<<dim3(S_LEN / 128, NHEAD, 2), 128, FB_SMEM>>>(
        qph, qpl, kph, kpl, vTh, vTl, ath, atl);

    // launch 3: final projection
    proj_out<<<dim3(8, 32), 128, SM_G>>>(ath, atl, Woh, Wol, bo, (float*)d_out);
}